// round 14
// baseline (speedup 1.0000x reference)
#include <cuda_runtime.h>
#include <cuda_fp16.h>
#include <math.h>
#include <stdint.h>

#define NBATCH 16
#define QN 900
#define QPAD 1024
#define HID 256
#define NBINS 36
#define NB2 1296
#define BIGV 1e9f

#define BM 128
#define KC 32
#define NCH (HID / KC)     // 8
#define NTI2 8
#define NTP2 36
#define KPADH 40
#define TILE_B (128 * KPADH * 2)
#define DYN_SMEM (2 * 4 * TILE_B)   // 81920 B

// ---------------- device globals ----------------
__device__ __half g_hi[NBATCH * QPAD * HID];
__device__ __half g_lo[NBATCH * QPAD * HID];
__device__ float g_ang[NBATCH * QN];
__device__ int   g_bin[NBATCH * QN];
__device__ unsigned long long g_seg[NBATCH * NB2];
__device__ unsigned int g_top4[NBATCH * 4];
__device__ float g_res[NBATCH * 4];
__device__ unsigned int g_bcnt[NBATCH];
__device__ unsigned int g_done;

// ---------------- ordered-float encoding ----------------
__device__ __forceinline__ unsigned encf(float f) {
    unsigned u = __float_as_uint(f);
    return (u & 0x80000000u) ? ~u : (u | 0x80000000u);
}
__device__ __forceinline__ float decf(unsigned u) {
    unsigned v = (u & 0x80000000u) ? (u ^ 0x80000000u) : ~u;
    return __uint_as_float(v);
}
__device__ __forceinline__ uint32_t smem_u32(const void* p) {
    uint32_t a;
    asm("{ .reg .u64 t; cvta.to.shared.u64 t, %1; cvt.u32.u64 %0, t; }"
        : "=r"(a) : "l"(p));
    return a;
}
__device__ __forceinline__ void mma_f16(float d[4], const uint32_t a[4],
                                        const uint32_t b[2]) {
    asm volatile(
        "mma.sync.aligned.m16n8k16.row.col.f32.f16.f16.f32 "
        "{%0,%1,%2,%3}, {%4,%5,%6,%7}, {%8,%9}, {%0,%1,%2,%3};"
        : "+f"(d[0]), "+f"(d[1]), "+f"(d[2]), "+f"(d[3])
        : "r"(a[0]), "r"(a[1]), "r"(a[2]), "r"(a[3]), "r"(b[0]), "r"(b[1]));
}
__device__ __forceinline__ void ldsm4(uint32_t r[4], uint32_t addr) {
    asm volatile("ldmatrix.sync.aligned.m8n8.x4.shared.b16 {%0,%1,%2,%3}, [%4];"
        : "=r"(r[0]), "=r"(r[1]), "=r"(r[2]), "=r"(r[3]) : "r"(addr));
}
__device__ __forceinline__ void cp16(uint32_t dst, const void* src) {
    asm volatile("cp.async.cg.shared.global [%0], [%1], 16;"
                 :: "r"(dst), "l"(src));
}
#define CP_COMMIT() asm volatile("cp.async.commit_group;" ::: "memory")
#define CP_WAIT1()  asm volatile("cp.async.wait_group 1;" ::: "memory")
#define CP_WAIT0()  asm volatile("cp.async.wait_group 0;" ::: "memory")

// ---------------- fuse: init + bins(8 parallel atan2) + normalize + hi/lo split ----------------
__global__ __launch_bounds__(256) void k_fuse(const float* __restrict__ qf,
                                              const float* __restrict__ pa,
                                              const float* __restrict__ W) {
    __shared__ int sbin[8];
    const int gid = blockIdx.x * 256 + threadIdx.x;   // grid 2048 x 256
    if (gid < NBATCH * NB2) g_seg[gid] = 0ULL;
    if (gid < NBATCH * 4)   g_top4[gid] = 0u;
    if (gid < NBATCH)       g_bcnt[gid] = 0u;
    if (gid == 0)           g_done = 0u;

    const int warp = threadIdx.x >> 5;
    const int lane = threadIdx.x & 31;
    const int row0 = blockIdx.x * 8;

    if (threadIdx.x < 8) {
        int row = row0 + threadIdx.x;
        int b = row >> 10, q = row & (QPAD - 1);
        int bin = 0;
        if (q < QN) {
            int bq = b * QN + q;
            float x = pa[bq * 2 + 0], y = pa[bq * 2 + 1];
            float a = (float)atan2((double)y, (double)x);
            const float TWO_PI_F = 6.283185307179586f;
            if (a < 0.0f) a += TWO_PI_F;
            const float BIN_SIZE_F = (float)(6.283185307179586476925287 / 36.0);
            bin = (int)(a / BIN_SIZE_F);
            bin = min(max(bin, 0), NBINS - 1);
            g_ang[bq] = a; g_bin[bq] = bin;
        }
        sbin[threadIdx.x] = bin;
    }
    __syncthreads();

    const int row = row0 + warp;
    const int b = row >> 10, q = row & (QPAD - 1);
    uint4* dh = (uint4*)(g_hi + (size_t)row * HID);
    uint4* dl = (uint4*)(g_lo + (size_t)row * HID);

    if (q >= QN) {
        uint4 z = make_uint4(0, 0, 0, 0);
        dh[lane] = z; dl[lane] = z;
        return;
    }
    const int bq = b * QN + q;
    const int bin = sbin[warp];

    const float4* qr = (const float4*)(qf + (size_t)bq * HID);
    const float4* wr = (const float4*)(W + (size_t)bin * HID);
    float4 f0 = qr[2 * lane], f1 = qr[2 * lane + 1];
    float4 w0 = wr[2 * lane], w1 = wr[2 * lane + 1];
    f0.x += w0.x; f0.y += w0.y; f0.z += w0.z; f0.w += w0.w;
    f1.x += w1.x; f1.y += w1.y; f1.z += w1.z; f1.w += w1.w;
    float ss = f0.x*f0.x + f0.y*f0.y + f0.z*f0.z + f0.w*f0.w
             + f1.x*f1.x + f1.y*f1.y + f1.z*f1.z + f1.w*f1.w;
    #pragma unroll
    for (int o = 16; o; o >>= 1) ss += __shfl_xor_sync(0xffffffffu, ss, o);
    float nrm = fmaxf(sqrtf(ss), 1e-12f);

    float v[8] = {f0.x, f0.y, f0.z, f0.w, f1.x, f1.y, f1.z, f1.w};
    __half oh[8], ol[8];
    #pragma unroll
    for (int i = 0; i < 8; i++) {
        float x = v[i] / nrm;
        __half h = __float2half_rn(x);
        float lo = x - __half2float(h);
        oh[i] = h;
        ol[i] = __float2half_rn(lo);
    }
    dh[lane] = *(const uint4*)oh;
    dl[lane] = *(const uint4*)ol;
}

// ---------------- block-reduce helpers (256 threads) ----------------
__device__ __forceinline__ float bsumf(float v, float* sh8, int tid) {
    #pragma unroll
    for (int o = 16; o; o >>= 1) v += __shfl_xor_sync(0xffffffffu, v, o);
    if ((tid & 31) == 0) sh8[tid >> 5] = v;
    __syncthreads();
    float r = sh8[0]+sh8[1]+sh8[2]+sh8[3]+sh8[4]+sh8[5]+sh8[6]+sh8[7];
    __syncthreads();
    return r;
}
__device__ __forceinline__ int bsumi(int v, int* sh8, int tid) {
    #pragma unroll
    for (int o = 16; o; o >>= 1) v += __shfl_xor_sync(0xffffffffu, v, o);
    if ((tid & 31) == 0) sh8[tid >> 5] = v;
    __syncthreads();
    int r = sh8[0]+sh8[1]+sh8[2]+sh8[3]+sh8[4]+sh8[5]+sh8[6]+sh8[7];
    __syncthreads();
    return r;
}
__device__ __forceinline__ void btop2(unsigned m1, unsigned m2,
                                      unsigned* s1, unsigned* s2, int tid,
                                      unsigned& o1, unsigned& o2) {
    #pragma unroll
    for (int o = 16; o; o >>= 1) {
        unsigned u1 = __shfl_xor_sync(0xffffffffu, m1, o);
        unsigned u2 = __shfl_xor_sync(0xffffffffu, m2, o);
        unsigned n1 = max(m1, u1);
        unsigned n2 = max(min(m1, u1), max(m2, u2));
        m1 = n1; m2 = n2;
    }
    if ((tid & 31) == 0) { s1[tid >> 5] = m1; s2[tid >> 5] = m2; }
    __syncthreads();
    unsigned t1 = 0, t2 = 0;
    #pragma unroll
    for (int w = 0; w < 8; w++) {
        unsigned a = s1[w], bb = s2[w];
        unsigned n1 = max(t1, a);
        unsigned n2 = max(min(t1, a), max(t2, bb));
        t1 = n1; t2 = n2;
    }
    __syncthreads();
    o1 = t1; o2 = t2;
}
__device__ __forceinline__ float quant2(float vmax, float vsec, int n) {
    if (n <= 0) return BIGV;
    float nf = (float)n;
    float q  = 1.0f - 1.0f / (nf + 1.0f);
    float pos = q * fmaxf(nf - 1.0f, 0.0f);
    int lo = (int)floorf(pos); lo = min(max(lo, 0), NB2 - 1);
    int hi = (int)ceilf(pos);  hi = min(max(hi, 0), NB2 - 1);
    float frac = pos - (float)lo;
    float vlo = (lo >= n - 1) ? vmax : vsec;
    float vhi = (hi >= n - 1) ? vmax : vsec;
    return vlo + (vhi - vlo) * frac;
}

// finalize shared-memory overlay on dynamic smem (GEMM buffers are dead)
struct FinSmem {
    float ssel[NB2], sdd[NB2], sai[NB2], saj[NB2];
    unsigned char svld[NB2], smF[NB2];
    float shf[8];
    int   shi[8];
    unsigned sh1[8], sh2[8];
    unsigned hist[256];
    unsigned warpTot[8];
    unsigned s_dig, s_bef;
};

// ---------------- pair kernel: GEMM + segment argmax + fused finalize ----------------
__global__ __launch_bounds__(256, 2) void k_pair(float* __restrict__ out) {
    __shared__ unsigned long long sseg[NB2];
    __shared__ int sbi[BM], sbj[BM];
    __shared__ unsigned stop4[4];
    __shared__ int s_isLast;
    extern __shared__ __half dynh[];
    const uint32_t dbu = smem_u32(dynh);

    const int b = blockIdx.y;
    int p = blockIdx.x;
    int ti = 0, rem = p;
    while (rem >= NTI2 - ti) { rem -= NTI2 - ti; ti++; }
    const int tj = ti + rem;
    const int i0 = ti * BM, j0 = tj * BM;
    const bool diag = (ti == tj);

    const int tid = threadIdx.x, wid = tid >> 5, lane = tid & 31;
    const int moff = (wid >> 2) * 64, noff = (wid & 3) * 32;
    const int lr = lane >> 2, lc = lane & 3;
    const int t8 = lane & 7, qd = lane >> 3;

    for (int s = tid; s < NB2; s += 256) sseg[s] = 0ULL;
    if (tid < 4) stop4[tid] = 0u;
    if (tid < BM) {
        int gi = i0 + tid; sbi[tid] = (gi < QN) ? g_bin[b * QN + gi] : 0;
        int gj = j0 + tid; sbj[tid] = (gj < QN) ? g_bin[b * QN + gj] : 0;
    }

    const __half* srcs[4];
    srcs[0] = g_hi + (size_t)(b * QPAD + i0) * HID;
    srcs[1] = g_lo + (size_t)(b * QPAD + i0) * HID;
    srcs[2] = g_hi + (size_t)(b * QPAD + j0) * HID;
    srcs[3] = g_lo + (size_t)(b * QPAD + j0) * HID;

    const int p0 = tid, p1 = tid + 256;
    const int pr0 = p0 >> 2, ps0 = p0 & 3;
    const int pr1 = p1 >> 2, ps1 = p1 & 3;
    const int nld = diag ? 2 : 4;   // diagonal tiles: B == A, skip B loads

    auto preload = [&](int ch, int stage) {
        for (int t = 0; t < nld; t++) {
            const __half* s = srcs[t] + ch * KC;
            uint32_t buf = dbu + (uint32_t)(((stage << 2) | t) * TILE_B);
            cp16(buf + (uint32_t)(pr0 * (KPADH * 2) + ps0 * 16),
                 s + (size_t)pr0 * HID + ps0 * 8);
            cp16(buf + (uint32_t)(pr1 * (KPADH * 2) + ps1 * 16),
                 s + (size_t)pr1 * HID + ps1 * 8);
        }
    };

    float acc[16][4];
    #pragma unroll
    for (int i = 0; i < 16; i++)
        #pragma unroll
        for (int e = 0; e < 4; e++) acc[i][e] = 0.0f;

    preload(0, 0);
    CP_COMMIT();

    const uint32_t aRow = (uint32_t)(moff + (qd & 1) * 8 + t8);
    const uint32_t aCol = (uint32_t)((qd >> 1) * 8);
    const uint32_t bRow = (uint32_t)(noff + (qd >> 1) * 8 + t8);
    const uint32_t bCol = (uint32_t)((qd & 1) * 8);

    #pragma unroll 1
    for (int ch = 0; ch < NCH; ch++) {
        const int cur = ch & 1;
        if (ch + 1 < NCH) {
            preload(ch + 1, cur ^ 1);
            CP_COMMIT();
            CP_WAIT1();
        } else {
            CP_WAIT0();
        }
        __syncthreads();

        const uint32_t bAh = dbu + (uint32_t)(((cur << 2) | 0) * TILE_B);
        const uint32_t bAl = dbu + (uint32_t)(((cur << 2) | 1) * TILE_B);
        const uint32_t bBh = diag ? bAh : (dbu + (uint32_t)(((cur << 2) | 2) * TILE_B));
        const uint32_t bBl = diag ? bAl : (dbu + (uint32_t)(((cur << 2) | 3) * TILE_B));

        #pragma unroll
        for (int ks = 0; ks < 2; ks++) {
            const uint32_t k0 = ks * 16;
            uint32_t bh[8], bl[8];
            #pragma unroll
            for (int ntp = 0; ntp < 2; ntp++) {
                uint32_t off = ((bRow + ntp * 16) * KPADH + k0 + bCol) * 2;
                ldsm4(bh + ntp * 4, bBh + off);
                ldsm4(bl + ntp * 4, bBl + off);
            }
            #pragma unroll
            for (int mt = 0; mt < 4; mt++) {
                uint32_t off = ((aRow + mt * 16) * KPADH + k0 + aCol) * 2;
                uint32_t ah[4], al[4];
                ldsm4(ah, bAh + off);
                ldsm4(al, bAl + off);
                // term-major issue order: dependency distance 4 (same acc
                // receives hh -> hl -> lh in order; numerics unchanged)
                #pragma unroll
                for (int nt = 0; nt < 4; nt++) {
                    const uint32_t* bhv = bh + (nt >> 1) * 4 + (nt & 1) * 2;
                    mma_f16(acc[mt * 4 + nt], ah, bhv);          // hh
                }
                #pragma unroll
                for (int nt = 0; nt < 4; nt++) {
                    const uint32_t* blv = bl + (nt >> 1) * 4 + (nt & 1) * 2;
                    mma_f16(acc[mt * 4 + nt], ah, blv);          // hl
                }
                #pragma unroll
                for (int nt = 0; nt < 4; nt++) {
                    const uint32_t* bhv = bh + (nt >> 1) * 4 + (nt & 1) * 2;
                    mma_f16(acc[mt * 4 + nt], al, bhv);          // lh
                }
            }
        }
        __syncthreads();
    }

    // epilogue: segment argmax + local top4
    unsigned lt[4] = {0u, 0u, 0u, 0u};
    #pragma unroll
    for (int mt = 0; mt < 4; mt++) {
        #pragma unroll
        for (int nt = 0; nt < 4; nt++) {
            #pragma unroll
            for (int e = 0; e < 4; e++) {
                int lrow = moff + mt * 16 + lr + ((e & 2) ? 8 : 0);
                int lcol = noff + nt * 8 + 2 * lc + (e & 1);
                int gi = i0 + lrow, gj = j0 + lcol;
                if (gi < QN && gj < QN && gi < gj) {
                    float v = acc[mt * 4 + nt][e];
                    unsigned ev = encf(v);
                    if (ev > lt[3]) {
                        if (ev > lt[0])      { lt[3]=lt[2]; lt[2]=lt[1]; lt[1]=lt[0]; lt[0]=ev; }
                        else if (ev > lt[1]) { lt[3]=lt[2]; lt[2]=lt[1]; lt[1]=ev; }
                        else if (ev > lt[2]) { lt[3]=lt[2]; lt[2]=ev; }
                        else                 { lt[3]=ev; }
                    }
                    int bi = sbi[lrow], bj = sbj[lcol];
                    int sgm = min(bi, bj) * NBINS + max(bi, bj);
                    unsigned long long key =
                        ((unsigned long long)ev << 32) |
                        (unsigned long long)(0xFFFFFFFFu - (unsigned)(gi * QN + gj));
                    if (key > sseg[sgm]) atomicMax(&sseg[sgm], key);
                }
            }
        }
    }
    #pragma unroll
    for (int q4 = 0; q4 < 4; q4++) {
        unsigned v = lt[q4];
        if (!v) break;
        #pragma unroll
        for (int sl = 0; sl < 4; sl++) {
            if (v > stop4[sl]) {
                unsigned old = atomicMax(&stop4[sl], v);
                v = min(v, old);
            }
            if (!v) break;
        }
    }
    __syncthreads();

    unsigned long long* gs = g_seg + (size_t)b * NB2;
    for (int s = tid; s < NB2; s += 256) {
        unsigned long long k = sseg[s];
        if (k && k > gs[s]) atomicMax(&gs[s], k);
    }
    if (tid == 0) {
        unsigned* gt = g_top4 + b * 4;
        #pragma unroll
        for (int q4 = 0; q4 < 4; q4++) {
            unsigned v = stop4[q4];
            if (!v) continue;
            for (int sl = 0; sl < 4; sl++) {
                if (v > gt[sl]) {
                    unsigned old = atomicMax(&gt[sl], v);
                    v = min(v, old);
                }
                if (!v) break;
            }
        }
    }
    __syncthreads();

    // ---- per-batch completion; last CTA runs finalize ----
    if (tid == 0) {
        __threadfence();
        unsigned old = atomicAdd(&g_bcnt[b], 1u);
        s_isLast = (old == NTP2 - 1) ? 1 : 0;
    }
    __syncthreads();
    if (!s_isLast) return;

    FinSmem* fsm = (FinSmem*)dynh;
    const float* ang = g_ang + b * QN;
    const float TWO_PI_F  = 6.283185307179586f;
    const float HALF_PI_F = 1.5707963267948966f;

    for (int s = tid; s < NB2; s += 256) {
        unsigned long long key = __ldcg(&g_seg[(size_t)b * NB2 + s]);
        float v = 0.f, ai = 0.f, aj = 0.f, d = 0.f;
        unsigned char vl = 0;
        if (key) {
            vl = 1;
            v = decf((unsigned)(key >> 32));
            unsigned ij = 0xFFFFFFFFu - (unsigned)key;
            int i = ij / QN, j = ij - i * QN;
            ai = ang[i]; aj = ang[j];
            float diff = fabsf(ai - aj);
            d = fminf(fminf(diff, TWO_PI_F - diff), HALF_PI_F);
        }
        fsm->ssel[s] = v; fsm->sai[s] = ai; fsm->saj[s] = aj;
        fsm->sdd[s] = d; fsm->svld[s] = vl;
    }
    __syncthreads();

    int c = 0; unsigned m1 = 0, m2 = 0;
    for (int s = tid; s < NB2; s += 256) {
        if (fsm->svld[s]) {
            c++;
            unsigned e = encf(fsm->ssel[s]);
            if (e > m1) { m2 = m1; m1 = e; } else if (e > m2) m2 = e;
        }
    }
    int S = bsumi(c, fsm->shi, tid);
    unsigned t1, t2; btop2(m1, m2, fsm->sh1, fsm->sh2, tid, t1, t2);
    float thr = quant2(decf(t1), decf(t2), S);

    c = 0;
    for (int s = tid; s < NB2; s += 256) {
        unsigned char m = (fsm->svld[s] && fsm->ssel[s] > thr) ? 1 : 0;
        fsm->smF[s] = m; c += m;
    }
    int c1 = bsumi(c, fsm->shi, tid);

    float th2 = decf(__ldcg(&g_top4[b * 4 + 3]));
    bool use_fb = (c1 < 2);
    c = 0;
    for (int s = tid; s < NB2; s += 256) {
        unsigned char m = use_fb ? ((fsm->svld[s] && fsm->ssel[s] >= th2) ? 1 : 0)
                                 : fsm->smF[s];
        fsm->smF[s] = m; c += m;
    }
    int cnt = bsumi(c, fsm->shi, tid);

    float med = BIGV;
    if (cnt > 0) {
        int kk = (cnt - 1) >> 1;
        unsigned prefix = 0;
        const int flane = tid & 31, w = tid >> 5;
        #pragma unroll
        for (int shift = 24; shift >= 0; shift -= 8) {
            fsm->hist[tid] = 0;
            __syncthreads();
            for (int s = tid; s < NB2; s += 256) {
                if (fsm->smF[s]) {
                    unsigned key = __float_as_uint(fsm->sdd[s]);
                    bool in = (shift == 24) || ((key >> (shift + 8)) == prefix);
                    if (in) atomicAdd(&fsm->hist[(key >> shift) & 255u], 1u);
                }
            }
            __syncthreads();
            unsigned my = fsm->hist[tid];
            unsigned v = my;
            #pragma unroll
            for (int o = 1; o < 32; o <<= 1) {
                unsigned u = __shfl_up_sync(0xffffffffu, v, o);
                if (flane >= o) v += u;
            }
            if (flane == 31) fsm->warpTot[w] = v;
            __syncthreads();
            unsigned off = 0;
            #pragma unroll
            for (int ww = 0; ww < 8; ww++) off += (ww < w) ? fsm->warpTot[ww] : 0u;
            unsigned cum = v + off, bef = cum - my;
            if ((int)cum > kk && (int)bef <= kk) { fsm->s_dig = (unsigned)tid; fsm->s_bef = bef; }
            __syncthreads();
            prefix = (prefix << 8) | fsm->s_dig;
            kk -= (int)fsm->s_bef;
            __syncthreads();
        }
        med = __uint_as_float(prefix);
    }
    float alpha = fminf(fmaxf(med, (float)(3.14159265358979323846 / 36.0)), HALF_PI_F);
    __syncthreads();

    float fs = 0.f; int nc = 0;
    for (int s = tid; s < NB2; s += 256) {
        if (fsm->smF[s] && fsm->sdd[s] <= alpha) {
            float ai = fsm->sai[s], aj = fsm->saj[s];
            float mean = atan2f((sinf(ai) + sinf(aj)) * 0.5f,
                                (cosf(ai) + cosf(aj)) * 0.5f);
            float d1 = fabsf(ai - mean); d1 = fminf(fminf(d1, TWO_PI_F - d1), HALF_PI_F);
            float d2 = fabsf(aj - mean); d2 = fminf(fminf(d2, TWO_PI_F - d2), HALF_PI_F);
            fs += d1 * d1 + d2 * d2;
            nc++;
        }
    }
    float coop_sum = bsumf(fs, fsm->shf, tid);
    int n_coop = bsumi(nc, fsm->shi, tid);
    float coop_b = coop_sum / (float)max(n_coop, 1);

    c = 0; m1 = 0; m2 = 0;
    for (int s = tid; s < NB2; s += 256) {
        if (fsm->smF[s] && fsm->sdd[s] > alpha) {
            c++;
            unsigned e = encf(fsm->ssel[s]);
            if (e > m1) { m2 = m1; m1 = e; } else if (e > m2) m2 = e;
        }
    }
    int n_comp = bsumi(c, fsm->shi, tid);
    btop2(m1, m2, fsm->sh1, fsm->sh2, tid, t1, t2);
    float margin = quant2(decf(t1), decf(t2), n_comp);

    fs = 0.f;
    for (int s = tid; s < NB2; s += 256) {
        if (fsm->smF[s] && fsm->sdd[s] > alpha) {
            float viol = fmaxf(fsm->ssel[s] - margin, 0.f);
            fs += viol * viol;
        }
    }
    float comp_sum = bsumf(fs, fsm->shf, tid);
    float comp_b = comp_sum / (float)max(n_comp, 1);

    if (tid == 0) {
        g_res[b * 4 + 0] = coop_b;
        g_res[b * 4 + 1] = comp_b;
        g_res[b * 4 + 2] = (cnt > 0) ? 1.0f : 0.0f;
        __threadfence();
        unsigned old = atomicAdd(&g_done, 1u);
        if (old == NBATCH - 1) {
            float cs = 0.f, ps = 0.f; int nv = 0;
            for (int bb = 0; bb < NBATCH; bb++) {
                float r0 = __ldcg(&g_res[bb * 4 + 0]);
                float r1 = __ldcg(&g_res[bb * 4 + 1]);
                float r2 = __ldcg(&g_res[bb * 4 + 2]);
                cs += r0; ps += r1;
                nv += (r2 > 0.f) ? 1 : 0;
            }
            float denom = (float)max(nv, 1);
            out[0] = cs / denom;
            out[1] = ps / denom;
        }
    }
}

// ---------------- launch ----------------
extern "C" void kernel_launch(void* const* d_in, const int* in_sizes, int n_in,
                              void* d_out, int out_size) {
    const float* qf = (const float*)d_in[0];   // [16,900,256]
    const float* pa = (const float*)d_in[1];   // [16,900,2]
    const float* W  = (const float*)d_in[2];   // [36,256]
    float* out = (float*)d_out;

    cudaFuncSetAttribute(k_pair, cudaFuncAttributeMaxDynamicSharedMemorySize, DYN_SMEM);

    k_fuse<<<NBATCH * QPAD / 8, 256>>>(qf, pa, W);
    dim3 g2(NTP2, NBATCH);
    k_pair<<<g2, 256, DYN_SMEM>>>(out);
}

// round 15
// speedup vs baseline: 1.0428x; 1.0428x over previous
#include <cuda_runtime.h>
#include <cuda_fp16.h>
#include <math.h>
#include <stdint.h>

#define NBATCH 16
#define QN 900
#define QPAD 1024
#define HID 256
#define NBINS 36
#define NB2 1296
#define BIGV 1e9f

#define BM 128
#define KC 32
#define NCH (HID / KC)     // 8
#define NTI2 8
#define NTP2 36
#define TILE_BYTES 8192              // 128 rows x 32 halves
#define STAGE_BYTES (4 * TILE_BYTES) // 32768
#define DYN_SMEM (2 * STAGE_BYTES)   // 65536

// ---------------- device globals ----------------
// chunk-major: [batch][chunk][row(QPAD)][32 halves]
__device__ __half g_hi[NBATCH * NCH * QPAD * KC];
__device__ __half g_lo[NBATCH * NCH * QPAD * KC];
__device__ float g_ang[NBATCH * QN];
__device__ int   g_bin[NBATCH * QN];
__device__ unsigned long long g_seg[NBATCH * NB2];
__device__ unsigned int g_top4[NBATCH * 4];
__device__ float g_res[NBATCH * 4];
__device__ unsigned int g_bcnt[NBATCH];
__device__ unsigned int g_done;

// ---------------- ordered-float encoding ----------------
__device__ __forceinline__ unsigned encf(float f) {
    unsigned u = __float_as_uint(f);
    return (u & 0x80000000u) ? ~u : (u | 0x80000000u);
}
__device__ __forceinline__ float decf(unsigned u) {
    unsigned v = (u & 0x80000000u) ? (u ^ 0x80000000u) : ~u;
    return __uint_as_float(v);
}
__device__ __forceinline__ uint32_t smem_u32(const void* p) {
    uint32_t a;
    asm("{ .reg .u64 t; cvta.to.shared.u64 t, %1; cvt.u32.u64 %0, t; }"
        : "=r"(a) : "l"(p));
    return a;
}
__device__ __forceinline__ void mma_f16(float d[4], const uint32_t a[4],
                                        const uint32_t b[2]) {
    asm volatile(
        "mma.sync.aligned.m16n8k16.row.col.f32.f16.f16.f32 "
        "{%0,%1,%2,%3}, {%4,%5,%6,%7}, {%8,%9}, {%0,%1,%2,%3};"
        : "+f"(d[0]), "+f"(d[1]), "+f"(d[2]), "+f"(d[3])
        : "r"(a[0]), "r"(a[1]), "r"(a[2]), "r"(a[3]), "r"(b[0]), "r"(b[1]));
}
__device__ __forceinline__ void ldsm4(uint32_t r[4], uint32_t addr) {
    asm volatile("ldmatrix.sync.aligned.m8n8.x4.shared.b16 {%0,%1,%2,%3}, [%4];"
        : "=r"(r[0]), "=r"(r[1]), "=r"(r[2]), "=r"(r[3]) : "r"(addr));
}
// bulk async copy global->shared with mbarrier completion (sm_90 baseline)
__device__ __forceinline__ void bulk_cp(uint32_t dst, const void* src,
                                        uint32_t bytes, uint32_t mbar) {
    asm volatile(
        "cp.async.bulk.shared::cta.global.mbarrier::complete_tx::bytes "
        "[%0], [%1], %2, [%3];"
        :: "r"(dst), "l"(src), "r"(bytes), "r"(mbar) : "memory");
}
#define MBAR_INIT(mbar, cnt) \
    asm volatile("mbarrier.init.shared.b64 [%0], %1;" :: "r"(mbar), "r"((uint32_t)(cnt)) : "memory")
#define MBAR_EXPECT(mbar, tx) \
    asm volatile("mbarrier.arrive.expect_tx.shared.b64 _, [%0], %1;" \
                 :: "r"(mbar), "r"((uint32_t)(tx)) : "memory")
#define MBAR_WAIT(mbar, par) do { \
    uint32_t _m = (mbar), _p = (par), _d; \
    asm volatile("{\n\t.reg .pred p;\n\t" \
        "mbarrier.try_wait.parity.acquire.cta.shared::cta.b64 p, [%1], %2;\n\t" \
        "selp.b32 %0, 1, 0, p;\n\t}" : "=r"(_d) : "r"(_m), "r"(_p) : "memory"); \
    if (!_d) { \
        asm volatile("{\n\t.reg .pred P1;\n\t" \
            "WL_%=:\n\t" \
            "mbarrier.try_wait.parity.acquire.cta.shared::cta.b64 P1, [%0], %1, 0x989680;\n\t" \
            "@P1 bra.uni WD_%=;\n\t" \
            "bra.uni WL_%=;\n\t" \
            "WD_%=:\n\t}" :: "r"(_m), "r"(_p) : "memory"); \
    } \
} while (0)

// ---------------- fuse: init + bins + normalize + hi/lo split (chunk-major, swizzled) ----------------
__global__ __launch_bounds__(256) void k_fuse(const float* __restrict__ qf,
                                              const float* __restrict__ pa,
                                              const float* __restrict__ W) {
    __shared__ int sbin[8];
    const int gid = blockIdx.x * 256 + threadIdx.x;   // grid 2048 x 256
    if (gid < NBATCH * NB2) g_seg[gid] = 0ULL;
    if (gid < NBATCH * 4)   g_top4[gid] = 0u;
    if (gid < NBATCH)       g_bcnt[gid] = 0u;
    if (gid == 0)           g_done = 0u;

    const int warp = threadIdx.x >> 5;
    const int lane = threadIdx.x & 31;
    const int row0 = blockIdx.x * 8;

    if (threadIdx.x < 8) {
        int row = row0 + threadIdx.x;
        int b = row >> 10, q = row & (QPAD - 1);
        int bin = 0;
        if (q < QN) {
            int bq = b * QN + q;
            float x = pa[bq * 2 + 0], y = pa[bq * 2 + 1];
            float a = (float)atan2((double)y, (double)x);
            const float TWO_PI_F = 6.283185307179586f;
            if (a < 0.0f) a += TWO_PI_F;
            const float BIN_SIZE_F = (float)(6.283185307179586476925287 / 36.0);
            bin = (int)(a / BIN_SIZE_F);
            bin = min(max(bin, 0), NBINS - 1);
            g_ang[bq] = a; g_bin[bq] = bin;
        }
        sbin[threadIdx.x] = bin;
    }
    __syncthreads();

    const int row = row0 + warp;
    const int b = row >> 10, q = row & (QPAD - 1);

    // this lane's destination: chunk = lane>>2, 16B-unit = lane&3 (swizzled)
    const int ch = lane >> 2, cu = lane & 3;
    const int cs = cu ^ ((q ^ (q >> 2)) & 3);
    const size_t doff = (((size_t)(b * NCH + ch) * QPAD + q) * KC) + cs * 8;

    if (q >= QN) {
        uint4 z = make_uint4(0, 0, 0, 0);
        *(uint4*)(g_hi + doff) = z;
        *(uint4*)(g_lo + doff) = z;
        return;
    }
    const int bq = b * QN + q;
    const int bin = sbin[warp];

    const float4* qr = (const float4*)(qf + (size_t)bq * HID);
    const float4* wr = (const float4*)(W + (size_t)bin * HID);
    float4 f0 = qr[2 * lane], f1 = qr[2 * lane + 1];      // k = 8*lane .. 8*lane+7
    float4 w0 = wr[2 * lane], w1 = wr[2 * lane + 1];
    f0.x += w0.x; f0.y += w0.y; f0.z += w0.z; f0.w += w0.w;
    f1.x += w1.x; f1.y += w1.y; f1.z += w1.z; f1.w += w1.w;
    float ss = f0.x*f0.x + f0.y*f0.y + f0.z*f0.z + f0.w*f0.w
             + f1.x*f1.x + f1.y*f1.y + f1.z*f1.z + f1.w*f1.w;
    #pragma unroll
    for (int o = 16; o; o >>= 1) ss += __shfl_xor_sync(0xffffffffu, ss, o);
    float nrm = fmaxf(sqrtf(ss), 1e-12f);

    float v[8] = {f0.x, f0.y, f0.z, f0.w, f1.x, f1.y, f1.z, f1.w};
    __half oh[8], ol[8];
    #pragma unroll
    for (int i = 0; i < 8; i++) {
        float x = v[i] / nrm;
        __half h = __float2half_rn(x);
        float lo = x - __half2float(h);
        oh[i] = h;
        ol[i] = __float2half_rn(lo);
    }
    *(uint4*)(g_hi + doff) = *(const uint4*)oh;
    *(uint4*)(g_lo + doff) = *(const uint4*)ol;
}

// ---------------- block-reduce helpers (256 threads) ----------------
__device__ __forceinline__ float bsumf(float v, float* sh8, int tid) {
    #pragma unroll
    for (int o = 16; o; o >>= 1) v += __shfl_xor_sync(0xffffffffu, v, o);
    if ((tid & 31) == 0) sh8[tid >> 5] = v;
    __syncthreads();
    float r = sh8[0]+sh8[1]+sh8[2]+sh8[3]+sh8[4]+sh8[5]+sh8[6]+sh8[7];
    __syncthreads();
    return r;
}
__device__ __forceinline__ int bsumi(int v, int* sh8, int tid) {
    #pragma unroll
    for (int o = 16; o; o >>= 1) v += __shfl_xor_sync(0xffffffffu, v, o);
    if ((tid & 31) == 0) sh8[tid >> 5] = v;
    __syncthreads();
    int r = sh8[0]+sh8[1]+sh8[2]+sh8[3]+sh8[4]+sh8[5]+sh8[6]+sh8[7];
    __syncthreads();
    return r;
}
__device__ __forceinline__ void btop2(unsigned m1, unsigned m2,
                                      unsigned* s1, unsigned* s2, int tid,
                                      unsigned& o1, unsigned& o2) {
    #pragma unroll
    for (int o = 16; o; o >>= 1) {
        unsigned u1 = __shfl_xor_sync(0xffffffffu, m1, o);
        unsigned u2 = __shfl_xor_sync(0xffffffffu, m2, o);
        unsigned n1 = max(m1, u1);
        unsigned n2 = max(min(m1, u1), max(m2, u2));
        m1 = n1; m2 = n2;
    }
    if ((tid & 31) == 0) { s1[tid >> 5] = m1; s2[tid >> 5] = m2; }
    __syncthreads();
    unsigned t1 = 0, t2 = 0;
    #pragma unroll
    for (int w = 0; w < 8; w++) {
        unsigned a = s1[w], bb = s2[w];
        unsigned n1 = max(t1, a);
        unsigned n2 = max(min(t1, a), max(t2, bb));
        t1 = n1; t2 = n2;
    }
    __syncthreads();
    o1 = t1; o2 = t2;
}
__device__ __forceinline__ float quant2(float vmax, float vsec, int n) {
    if (n <= 0) return BIGV;
    float nf = (float)n;
    float q  = 1.0f - 1.0f / (nf + 1.0f);
    float pos = q * fmaxf(nf - 1.0f, 0.0f);
    int lo = (int)floorf(pos); lo = min(max(lo, 0), NB2 - 1);
    int hi = (int)ceilf(pos);  hi = min(max(hi, 0), NB2 - 1);
    float frac = pos - (float)lo;
    float vlo = (lo >= n - 1) ? vmax : vsec;
    float vhi = (hi >= n - 1) ? vmax : vsec;
    return vlo + (vhi - vlo) * frac;
}

// finalize shared-memory overlay on dynamic smem (GEMM buffers are dead)
struct FinSmem {
    float ssel[NB2], sdd[NB2], sai[NB2], saj[NB2];
    unsigned char svld[NB2], smF[NB2];
    float shf[8];
    int   shi[8];
    unsigned sh1[8], sh2[8];
    unsigned hist[256];
    unsigned warpTot[8];
    unsigned s_dig, s_bef;
};

// ---------------- pair kernel: GEMM (bulk-copy pipeline) + argmax + fused finalize ----------------
__global__ __launch_bounds__(256, 2) void k_pair(float* __restrict__ out) {
    __shared__ unsigned long long sseg[NB2];
    __shared__ int sbi[BM], sbj[BM];
    __shared__ unsigned stop4[4];
    __shared__ int s_isLast;
    __shared__ __align__(8) unsigned long long s_mbar[2];
    extern __shared__ __half dynh[];
    const uint32_t dbu = smem_u32(dynh);
    const uint32_t mb0 = smem_u32(&s_mbar[0]);
    const uint32_t mb1 = smem_u32(&s_mbar[1]);

    const int b = blockIdx.y;
    int p = blockIdx.x;
    int ti = 0, rem = p;
    while (rem >= NTI2 - ti) { rem -= NTI2 - ti; ti++; }
    const int tj = ti + rem;
    const int i0 = ti * BM, j0 = tj * BM;
    const bool diag = (ti == tj);
    const uint32_t txBytes = diag ? (2 * TILE_BYTES) : (4 * TILE_BYTES);

    const int tid = threadIdx.x, wid = tid >> 5, lane = tid & 31;
    const int moff = (wid >> 2) * 64, noff = (wid & 3) * 32;
    const int lr = lane >> 2, lc = lane & 3;
    const int t8 = lane & 7, qd = lane >> 3;

    for (int s = tid; s < NB2; s += 256) sseg[s] = 0ULL;
    if (tid < 4) stop4[tid] = 0u;
    if (tid < BM) {
        int gi = i0 + tid; sbi[tid] = (gi < QN) ? g_bin[b * QN + gi] : 0;
        int gj = j0 + tid; sbj[tid] = (gj < QN) ? g_bin[b * QN + gj] : 0;
    }
    if (tid == 0) { MBAR_INIT(mb0, 1); MBAR_INIT(mb1, 1); }
    __syncthreads();

    // chunk-major global tile sources (each tile-chunk = contiguous 8KB)
    auto issue = [&](int ch, int stage) {
        uint32_t mbar = stage ? mb1 : mb0;
        uint32_t sb = dbu + stage * STAGE_BYTES;
        MBAR_EXPECT(mbar, txBytes);
        const size_t baseA = ((size_t)(b * NCH + ch) * QPAD + i0) * KC;
        bulk_cp(sb,              g_hi + baseA, TILE_BYTES, mbar);
        bulk_cp(sb + TILE_BYTES, g_lo + baseA, TILE_BYTES, mbar);
        if (!diag) {
            const size_t baseB = ((size_t)(b * NCH + ch) * QPAD + j0) * KC;
            bulk_cp(sb + 2 * TILE_BYTES, g_hi + baseB, TILE_BYTES, mbar);
            bulk_cp(sb + 3 * TILE_BYTES, g_lo + baseB, TILE_BYTES, mbar);
        }
    };

    float acc[16][4];
    #pragma unroll
    for (int i = 0; i < 16; i++)
        #pragma unroll
        for (int e = 0; e < 4; e++) acc[i][e] = 0.0f;

    if (tid == 0) { issue(0, 0); issue(1, 1); }

    const uint32_t aRow = (uint32_t)(moff + (qd & 1) * 8 + t8);
    const uint32_t bRow = (uint32_t)(noff + (qd >> 1) * 8 + t8);
    const uint32_t aCu = (uint32_t)(qd >> 1);   // base 16B-unit for A
    const uint32_t bCu = (uint32_t)(qd & 1);    // base 16B-unit for B

    #pragma unroll 1
    for (int ch = 0; ch < NCH; ch++) {
        const int st = ch & 1;
        MBAR_WAIT(st ? mb1 : mb0, (ch >> 1) & 1);
        __syncthreads();

        const uint32_t sb = dbu + st * STAGE_BYTES;
        const uint32_t bAh = sb;
        const uint32_t bAl = sb + TILE_BYTES;
        const uint32_t bBh = diag ? bAh : (sb + 2 * TILE_BYTES);
        const uint32_t bBl = diag ? bAl : (sb + 3 * TILE_BYTES);

        #pragma unroll
        for (int ks = 0; ks < 2; ks++) {
            uint32_t bh[8], bl[8];
            #pragma unroll
            for (int ntp = 0; ntp < 2; ntp++) {
                uint32_t row = bRow + ntp * 16;
                uint32_t c = (uint32_t)(ks * 2) + bCu;
                c ^= (row ^ (row >> 2)) & 3u;
                uint32_t off = row * 64 + c * 16;
                ldsm4(bh + ntp * 4, bBh + off);
                ldsm4(bl + ntp * 4, bBl + off);
            }
            #pragma unroll
            for (int mt = 0; mt < 4; mt++) {
                uint32_t row = aRow + mt * 16;
                uint32_t c = (uint32_t)(ks * 2) + aCu;
                c ^= (row ^ (row >> 2)) & 3u;
                uint32_t off = row * 64 + c * 16;
                uint32_t ah[4], al[4];
                ldsm4(ah, bAh + off);
                ldsm4(al, bAl + off);
                #pragma unroll
                for (int nt = 0; nt < 4; nt++) {
                    const uint32_t* bhv = bh + (nt >> 1) * 4 + (nt & 1) * 2;
                    const uint32_t* blv = bl + (nt >> 1) * 4 + (nt & 1) * 2;
                    mma_f16(acc[mt * 4 + nt], ah, bhv);
                    mma_f16(acc[mt * 4 + nt], ah, blv);
                    mma_f16(acc[mt * 4 + nt], al, bhv);
                }
            }
        }
        __syncthreads();
        if (ch + 2 < NCH && tid == 0) issue(ch + 2, st);
    }

    // epilogue: segment argmax + local top4
    unsigned lt[4] = {0u, 0u, 0u, 0u};
    #pragma unroll
    for (int mt = 0; mt < 4; mt++) {
        #pragma unroll
        for (int nt = 0; nt < 4; nt++) {
            #pragma unroll
            for (int e = 0; e < 4; e++) {
                int lrow = moff + mt * 16 + lr + ((e & 2) ? 8 : 0);
                int lcol = noff + nt * 8 + 2 * lc + (e & 1);
                int gi = i0 + lrow, gj = j0 + lcol;
                if (gi < QN && gj < QN && gi < gj) {
                    float v = acc[mt * 4 + nt][e];
                    unsigned ev = encf(v);
                    if (ev > lt[3]) {
                        if (ev > lt[0])      { lt[3]=lt[2]; lt[2]=lt[1]; lt[1]=lt[0]; lt[0]=ev; }
                        else if (ev > lt[1]) { lt[3]=lt[2]; lt[2]=lt[1]; lt[1]=ev; }
                        else if (ev > lt[2]) { lt[3]=lt[2]; lt[2]=ev; }
                        else                 { lt[3]=ev; }
                    }
                    int bi = sbi[lrow], bj = sbj[lcol];
                    int sgm = min(bi, bj) * NBINS + max(bi, bj);
                    unsigned long long key =
                        ((unsigned long long)ev << 32) |
                        (unsigned long long)(0xFFFFFFFFu - (unsigned)(gi * QN + gj));
                    if (key > sseg[sgm]) atomicMax(&sseg[sgm], key);
                }
            }
        }
    }
    #pragma unroll
    for (int q4 = 0; q4 < 4; q4++) {
        unsigned v = lt[q4];
        if (!v) break;
        #pragma unroll
        for (int sl = 0; sl < 4; sl++) {
            if (v > stop4[sl]) {
                unsigned old = atomicMax(&stop4[sl], v);
                v = min(v, old);
            }
            if (!v) break;
        }
    }
    __syncthreads();

    unsigned long long* gs = g_seg + (size_t)b * NB2;
    for (int s = tid; s < NB2; s += 256) {
        unsigned long long k = sseg[s];
        if (k && k > gs[s]) atomicMax(&gs[s], k);
    }
    if (tid == 0) {
        unsigned* gt = g_top4 + b * 4;
        #pragma unroll
        for (int q4 = 0; q4 < 4; q4++) {
            unsigned v = stop4[q4];
            if (!v) continue;
            for (int sl = 0; sl < 4; sl++) {
                if (v > gt[sl]) {
                    unsigned old = atomicMax(&gt[sl], v);
                    v = min(v, old);
                }
                if (!v) break;
            }
        }
    }
    __syncthreads();

    // ---- per-batch completion; last CTA runs finalize ----
    if (tid == 0) {
        __threadfence();
        unsigned old = atomicAdd(&g_bcnt[b], 1u);
        s_isLast = (old == NTP2 - 1) ? 1 : 0;
    }
    __syncthreads();
    if (!s_isLast) return;

    FinSmem* fsm = (FinSmem*)dynh;
    const float* ang = g_ang + b * QN;
    const float TWO_PI_F  = 6.283185307179586f;
    const float HALF_PI_F = 1.5707963267948966f;

    for (int s = tid; s < NB2; s += 256) {
        unsigned long long key = __ldcg(&g_seg[(size_t)b * NB2 + s]);
        float v = 0.f, ai = 0.f, aj = 0.f, d = 0.f;
        unsigned char vl = 0;
        if (key) {
            vl = 1;
            v = decf((unsigned)(key >> 32));
            unsigned ij = 0xFFFFFFFFu - (unsigned)key;
            int i = ij / QN, j = ij - i * QN;
            ai = ang[i]; aj = ang[j];
            float diff = fabsf(ai - aj);
            d = fminf(fminf(diff, TWO_PI_F - diff), HALF_PI_F);
        }
        fsm->ssel[s] = v; fsm->sai[s] = ai; fsm->saj[s] = aj;
        fsm->sdd[s] = d; fsm->svld[s] = vl;
    }
    __syncthreads();

    int c = 0; unsigned m1 = 0, m2 = 0;
    for (int s = tid; s < NB2; s += 256) {
        if (fsm->svld[s]) {
            c++;
            unsigned e = encf(fsm->ssel[s]);
            if (e > m1) { m2 = m1; m1 = e; } else if (e > m2) m2 = e;
        }
    }
    int S = bsumi(c, fsm->shi, tid);
    unsigned t1, t2; btop2(m1, m2, fsm->sh1, fsm->sh2, tid, t1, t2);
    float thr = quant2(decf(t1), decf(t2), S);

    c = 0;
    for (int s = tid; s < NB2; s += 256) {
        unsigned char m = (fsm->svld[s] && fsm->ssel[s] > thr) ? 1 : 0;
        fsm->smF[s] = m; c += m;
    }
    int c1 = bsumi(c, fsm->shi, tid);

    float th2 = decf(__ldcg(&g_top4[b * 4 + 3]));
    bool use_fb = (c1 < 2);
    c = 0;
    for (int s = tid; s < NB2; s += 256) {
        unsigned char m = use_fb ? ((fsm->svld[s] && fsm->ssel[s] >= th2) ? 1 : 0)
                                 : fsm->smF[s];
        fsm->smF[s] = m; c += m;
    }
    int cnt = bsumi(c, fsm->shi, tid);

    float med = BIGV;
    if (cnt > 0) {
        int kk = (cnt - 1) >> 1;
        unsigned prefix = 0;
        const int flane = tid & 31, w = tid >> 5;
        #pragma unroll
        for (int shift = 24; shift >= 0; shift -= 8) {
            fsm->hist[tid] = 0;
            __syncthreads();
            for (int s = tid; s < NB2; s += 256) {
                if (fsm->smF[s]) {
                    unsigned key = __float_as_uint(fsm->sdd[s]);
                    bool in = (shift == 24) || ((key >> (shift + 8)) == prefix);
                    if (in) atomicAdd(&fsm->hist[(key >> shift) & 255u], 1u);
                }
            }
            __syncthreads();
            unsigned my = fsm->hist[tid];
            unsigned v = my;
            #pragma unroll
            for (int o = 1; o < 32; o <<= 1) {
                unsigned u = __shfl_up_sync(0xffffffffu, v, o);
                if (flane >= o) v += u;
            }
            if (flane == 31) fsm->warpTot[w] = v;
            __syncthreads();
            unsigned off = 0;
            #pragma unroll
            for (int ww = 0; ww < 8; ww++) off += (ww < w) ? fsm->warpTot[ww] : 0u;
            unsigned cum = v + off, bef = cum - my;
            if ((int)cum > kk && (int)bef <= kk) { fsm->s_dig = (unsigned)tid; fsm->s_bef = bef; }
            __syncthreads();
            prefix = (prefix << 8) | fsm->s_dig;
            kk -= (int)fsm->s_bef;
            __syncthreads();
        }
        med = __uint_as_float(prefix);
    }
    float alpha = fminf(fmaxf(med, (float)(3.14159265358979323846 / 36.0)), HALF_PI_F);
    __syncthreads();

    float fs = 0.f; int nc = 0;
    for (int s = tid; s < NB2; s += 256) {
        if (fsm->smF[s] && fsm->sdd[s] <= alpha) {
            float ai = fsm->sai[s], aj = fsm->saj[s];
            float mean = atan2f((sinf(ai) + sinf(aj)) * 0.5f,
                                (cosf(ai) + cosf(aj)) * 0.5f);
            float d1 = fabsf(ai - mean); d1 = fminf(fminf(d1, TWO_PI_F - d1), HALF_PI_F);
            float d2 = fabsf(aj - mean); d2 = fminf(fminf(d2, TWO_PI_F - d2), HALF_PI_F);
            fs += d1 * d1 + d2 * d2;
            nc++;
        }
    }
    float coop_sum = bsumf(fs, fsm->shf, tid);
    int n_coop = bsumi(nc, fsm->shi, tid);
    float coop_b = coop_sum / (float)max(n_coop, 1);

    c = 0; m1 = 0; m2 = 0;
    for (int s = tid; s < NB2; s += 256) {
        if (fsm->smF[s] && fsm->sdd[s] > alpha) {
            c++;
            unsigned e = encf(fsm->ssel[s]);
            if (e > m1) { m2 = m1; m1 = e; } else if (e > m2) m2 = e;
        }
    }
    int n_comp = bsumi(c, fsm->shi, tid);
    btop2(m1, m2, fsm->sh1, fsm->sh2, tid, t1, t2);
    float margin = quant2(decf(t1), decf(t2), n_comp);

    fs = 0.f;
    for (int s = tid; s < NB2; s += 256) {
        if (fsm->smF[s] && fsm->sdd[s] > alpha) {
            float viol = fmaxf(fsm->ssel[s] - margin, 0.f);
            fs += viol * viol;
        }
    }
    float comp_sum = bsumf(fs, fsm->shf, tid);
    float comp_b = comp_sum / (float)max(n_comp, 1);

    if (tid == 0) {
        g_res[b * 4 + 0] = coop_b;
        g_res[b * 4 + 1] = comp_b;
        g_res[b * 4 + 2] = (cnt > 0) ? 1.0f : 0.0f;
        __threadfence();
        unsigned old = atomicAdd(&g_done, 1u);
        if (old == NBATCH - 1) {
            float cs = 0.f, ps = 0.f; int nv = 0;
            for (int bb = 0; bb < NBATCH; bb++) {
                float r0 = __ldcg(&g_res[bb * 4 + 0]);
                float r1 = __ldcg(&g_res[bb * 4 + 1]);
                float r2 = __ldcg(&g_res[bb * 4 + 2]);
                cs += r0; ps += r1;
                nv += (r2 > 0.f) ? 1 : 0;
            }
            float denom = (float)max(nv, 1);
            out[0] = cs / denom;
            out[1] = ps / denom;
        }
    }
}

// ---------------- launch ----------------
extern "C" void kernel_launch(void* const* d_in, const int* in_sizes, int n_in,
                              void* d_out, int out_size) {
    const float* qf = (const float*)d_in[0];   // [16,900,256]
    const float* pa = (const float*)d_in[1];   // [16,900,2]
    const float* W  = (const float*)d_in[2];   // [36,256]
    float* out = (float*)d_out;

    cudaFuncSetAttribute(k_pair, cudaFuncAttributeMaxDynamicSharedMemorySize, DYN_SMEM);

    k_fuse<<<NBATCH * QPAD / 8, 256>>>(qf, pa, W);
    dim3 g2(NTP2, NBATCH);
    k_pair<<<g2, 256, DYN_SMEM>>>(out);
}

// round 16
// speedup vs baseline: 1.0539x; 1.0106x over previous
#include <cuda_runtime.h>
#include <cuda_fp16.h>
#include <math.h>
#include <stdint.h>

#define NBATCH 16
#define QN 900
#define QPAD 1024
#define HID 256
#define NBINS 36
#define NB2 1296
#define BIGV 1e9f

#define KC 32
#define NCH (HID / KC)       // 8
#define NTI2 8               // 128-row tiles
#define NTJ 16               // 64-col tiles
#define NTPB 72              // tiles per batch: sum_{ti}(16-2ti)
#define A_TILE 8192          // 128 rows x 32 halves x 2B
#define B_TILE 4096          // 64 rows x 32 halves x 2B
#define STAGE_BYTES (2 * A_TILE + 2 * B_TILE)   // 24576
#define DYN_SMEM (2 * STAGE_BYTES)              // 49152

// ---------------- device globals ----------------
// chunk-major: [batch][chunk][row(QPAD)][32 halves]
__device__ __half g_hi[NBATCH * NCH * QPAD * KC];
__device__ __half g_lo[NBATCH * NCH * QPAD * KC];
__device__ float g_ang[NBATCH * QN];
__device__ int   g_bin[NBATCH * QN];
__device__ unsigned long long g_seg[NBATCH * NB2];
__device__ unsigned int g_top4[NBATCH * 4];
__device__ float g_res[NBATCH * 4];
__device__ unsigned int g_bcnt[NBATCH];
__device__ unsigned int g_done;

// ---------------- ordered-float encoding ----------------
__device__ __forceinline__ unsigned encf(float f) {
    unsigned u = __float_as_uint(f);
    return (u & 0x80000000u) ? ~u : (u | 0x80000000u);
}
__device__ __forceinline__ float decf(unsigned u) {
    unsigned v = (u & 0x80000000u) ? (u ^ 0x80000000u) : ~u;
    return __uint_as_float(v);
}
__device__ __forceinline__ uint32_t smem_u32(const void* p) {
    uint32_t a;
    asm("{ .reg .u64 t; cvta.to.shared.u64 t, %1; cvt.u32.u64 %0, t; }"
        : "=r"(a) : "l"(p));
    return a;
}
__device__ __forceinline__ void mma_f16(float d[4], const uint32_t a[4],
                                        const uint32_t b[2]) {
    asm volatile(
        "mma.sync.aligned.m16n8k16.row.col.f32.f16.f16.f32 "
        "{%0,%1,%2,%3}, {%4,%5,%6,%7}, {%8,%9}, {%0,%1,%2,%3};"
        : "+f"(d[0]), "+f"(d[1]), "+f"(d[2]), "+f"(d[3])
        : "r"(a[0]), "r"(a[1]), "r"(a[2]), "r"(a[3]), "r"(b[0]), "r"(b[1]));
}
__device__ __forceinline__ void ldsm4(uint32_t r[4], uint32_t addr) {
    asm volatile("ldmatrix.sync.aligned.m8n8.x4.shared.b16 {%0,%1,%2,%3}, [%4];"
        : "=r"(r[0]), "=r"(r[1]), "=r"(r[2]), "=r"(r[3]) : "r"(addr));
}
__device__ __forceinline__ void bulk_cp(uint32_t dst, const void* src,
                                        uint32_t bytes, uint32_t mbar) {
    asm volatile(
        "cp.async.bulk.shared::cta.global.mbarrier::complete_tx::bytes "
        "[%0], [%1], %2, [%3];"
        :: "r"(dst), "l"(src), "r"(bytes), "r"(mbar) : "memory");
}
#define MBAR_INIT(mbar, cnt) \
    asm volatile("mbarrier.init.shared.b64 [%0], %1;" :: "r"(mbar), "r"((uint32_t)(cnt)) : "memory")
#define MBAR_EXPECT(mbar, tx) \
    asm volatile("mbarrier.arrive.expect_tx.shared.b64 _, [%0], %1;" \
                 :: "r"(mbar), "r"((uint32_t)(tx)) : "memory")
#define MBAR_WAIT(mbar, par) do { \
    uint32_t _m = (mbar), _p = (par), _d; \
    asm volatile("{\n\t.reg .pred p;\n\t" \
        "mbarrier.try_wait.parity.acquire.cta.shared::cta.b64 p, [%1], %2;\n\t" \
        "selp.b32 %0, 1, 0, p;\n\t}" : "=r"(_d) : "r"(_m), "r"(_p) : "memory"); \
    if (!_d) { \
        asm volatile("{\n\t.reg .pred P1;\n\t" \
            "WL_%=:\n\t" \
            "mbarrier.try_wait.parity.acquire.cta.shared::cta.b64 P1, [%0], %1, 0x989680;\n\t" \
            "@P1 bra.uni WD_%=;\n\t" \
            "bra.uni WL_%=;\n\t" \
            "WD_%=:\n\t}" :: "r"(_m), "r"(_p) : "memory"); \
    } \
} while (0)

// ---------------- fuse: init + bins + normalize + hi/lo split (chunk-major, swizzled) ----------------
__global__ __launch_bounds__(256) void k_fuse(const float* __restrict__ qf,
                                              const float* __restrict__ pa,
                                              const float* __restrict__ W) {
    __shared__ int sbin[8];
    const int gid = blockIdx.x * 256 + threadIdx.x;
    if (gid < NBATCH * NB2) g_seg[gid] = 0ULL;
    if (gid < NBATCH * 4)   g_top4[gid] = 0u;
    if (gid < NBATCH)       g_bcnt[gid] = 0u;
    if (gid == 0)           g_done = 0u;

    const int warp = threadIdx.x >> 5;
    const int lane = threadIdx.x & 31;
    const int row0 = blockIdx.x * 8;

    if (threadIdx.x < 8) {
        int row = row0 + threadIdx.x;
        int b = row >> 10, q = row & (QPAD - 1);
        int bin = 0;
        if (q < QN) {
            int bq = b * QN + q;
            float x = pa[bq * 2 + 0], y = pa[bq * 2 + 1];
            float a = (float)atan2((double)y, (double)x);
            const float TWO_PI_F = 6.283185307179586f;
            if (a < 0.0f) a += TWO_PI_F;
            const float BIN_SIZE_F = (float)(6.283185307179586476925287 / 36.0);
            bin = (int)(a / BIN_SIZE_F);
            bin = min(max(bin, 0), NBINS - 1);
            g_ang[bq] = a; g_bin[bq] = bin;
        }
        sbin[threadIdx.x] = bin;
    }
    __syncthreads();

    const int row = row0 + warp;
    const int b = row >> 10, q = row & (QPAD - 1);

    const int ch = lane >> 2, cu = lane & 3;
    const int cs = cu ^ ((q ^ (q >> 2)) & 3);
    const size_t doff = (((size_t)(b * NCH + ch) * QPAD + q) * KC) + cs * 8;

    if (q >= QN) {
        uint4 z = make_uint4(0, 0, 0, 0);
        *(uint4*)(g_hi + doff) = z;
        *(uint4*)(g_lo + doff) = z;
        return;
    }
    const int bq = b * QN + q;
    const int bin = sbin[warp];

    const float4* qr = (const float4*)(qf + (size_t)bq * HID);
    const float4* wr = (const float4*)(W + (size_t)bin * HID);
    float4 f0 = qr[2 * lane], f1 = qr[2 * lane + 1];
    float4 w0 = wr[2 * lane], w1 = wr[2 * lane + 1];
    f0.x += w0.x; f0.y += w0.y; f0.z += w0.z; f0.w += w0.w;
    f1.x += w1.x; f1.y += w1.y; f1.z += w1.z; f1.w += w1.w;
    float ss = f0.x*f0.x + f0.y*f0.y + f0.z*f0.z + f0.w*f0.w
             + f1.x*f1.x + f1.y*f1.y + f1.z*f1.z + f1.w*f1.w;
    #pragma unroll
    for (int o = 16; o; o >>= 1) ss += __shfl_xor_sync(0xffffffffu, ss, o);
    float nrm = fmaxf(sqrtf(ss), 1e-12f);

    float v[8] = {f0.x, f0.y, f0.z, f0.w, f1.x, f1.y, f1.z, f1.w};
    __half oh[8], ol[8];
    #pragma unroll
    for (int i = 0; i < 8; i++) {
        float x = v[i] / nrm;
        __half h = __float2half_rn(x);
        float lo = x - __half2float(h);
        oh[i] = h;
        ol[i] = __float2half_rn(lo);
    }
    *(uint4*)(g_hi + doff) = *(const uint4*)oh;
    *(uint4*)(g_lo + doff) = *(const uint4*)ol;
}

// ---------------- block-reduce helpers (256 threads) ----------------
__device__ __forceinline__ float bsumf(float v, float* sh8, int tid) {
    #pragma unroll
    for (int o = 16; o; o >>= 1) v += __shfl_xor_sync(0xffffffffu, v, o);
    if ((tid & 31) == 0) sh8[tid >> 5] = v;
    __syncthreads();
    float r = sh8[0]+sh8[1]+sh8[2]+sh8[3]+sh8[4]+sh8[5]+sh8[6]+sh8[7];
    __syncthreads();
    return r;
}
__device__ __forceinline__ int bsumi(int v, int* sh8, int tid) {
    #pragma unroll
    for (int o = 16; o; o >>= 1) v += __shfl_xor_sync(0xffffffffu, v, o);
    if ((tid & 31) == 0) sh8[tid >> 5] = v;
    __syncthreads();
    int r = sh8[0]+sh8[1]+sh8[2]+sh8[3]+sh8[4]+sh8[5]+sh8[6]+sh8[7];
    __syncthreads();
    return r;
}
__device__ __forceinline__ void btop2(unsigned m1, unsigned m2,
                                      unsigned* s1, unsigned* s2, int tid,
                                      unsigned& o1, unsigned& o2) {
    #pragma unroll
    for (int o = 16; o; o >>= 1) {
        unsigned u1 = __shfl_xor_sync(0xffffffffu, m1, o);
        unsigned u2 = __shfl_xor_sync(0xffffffffu, m2, o);
        unsigned n1 = max(m1, u1);
        unsigned n2 = max(min(m1, u1), max(m2, u2));
        m1 = n1; m2 = n2;
    }
    if ((tid & 31) == 0) { s1[tid >> 5] = m1; s2[tid >> 5] = m2; }
    __syncthreads();
    unsigned t1 = 0, t2 = 0;
    #pragma unroll
    for (int w = 0; w < 8; w++) {
        unsigned a = s1[w], bb = s2[w];
        unsigned n1 = max(t1, a);
        unsigned n2 = max(min(t1, a), max(t2, bb));
        t1 = n1; t2 = n2;
    }
    __syncthreads();
    o1 = t1; o2 = t2;
}
__device__ __forceinline__ float quant2(float vmax, float vsec, int n) {
    if (n <= 0) return BIGV;
    float nf = (float)n;
    float q  = 1.0f - 1.0f / (nf + 1.0f);
    float pos = q * fmaxf(nf - 1.0f, 0.0f);
    int lo = (int)floorf(pos); lo = min(max(lo, 0), NB2 - 1);
    int hi = (int)ceilf(pos);  hi = min(max(hi, 0), NB2 - 1);
    float frac = pos - (float)lo;
    float vlo = (lo >= n - 1) ? vmax : vsec;
    float vhi = (hi >= n - 1) ? vmax : vsec;
    return vlo + (vhi - vlo) * frac;
}

// finalize shared-memory overlay on dynamic smem (GEMM buffers dead)
struct FinSmem {
    float ssel[NB2], sdd[NB2], sai[NB2], saj[NB2];
    unsigned char svld[NB2], smF[NB2];
    float shf[8];
    int   shi[8];
    unsigned sh1[8], sh2[8];
    unsigned hist[256];
    unsigned warpTot[8];
    unsigned s_dig, s_bef;
};

// ---------------- pair kernel: 128x64 tiles, 3 CTAs/SM ----------------
__global__ __launch_bounds__(256, 3) void k_pair(float* __restrict__ out) {
    __shared__ unsigned long long sseg[NB2];
    __shared__ int sbi[128], sbj[64];
    __shared__ unsigned stop4[4];
    __shared__ int s_isLast;
    __shared__ __align__(8) unsigned long long s_mbar[2];
    extern __shared__ __half dynh[];
    const uint32_t dbu = smem_u32(dynh);
    const uint32_t mb0 = smem_u32(&s_mbar[0]);
    const uint32_t mb1 = smem_u32(&s_mbar[1]);

    const int b = blockIdx.y;
    int p = blockIdx.x;
    int ti = 0, rem = p;
    while (rem >= NTJ - 2 * ti) { rem -= NTJ - 2 * ti; ti++; }
    const int cj = 2 * ti + rem;
    const int i0 = ti * 128, j0 = cj * 64;
    const int dlt = cj - 2 * ti;              // 0/1 -> B aliases A
    const bool diag = (dlt < 2);
    const uint32_t txBytes = diag ? (2 * A_TILE) : (2 * A_TILE + 2 * B_TILE);

    const int tid = threadIdx.x, wid = tid >> 5, lane = tid & 31;
    const int moff = (wid >> 1) * 32, noff = (wid & 1) * 32;
    const int lr = lane >> 2, lc = lane & 3;
    const int t8 = lane & 7, qd = lane >> 3;

    for (int s = tid; s < NB2; s += 256) sseg[s] = 0ULL;
    if (tid < 4) stop4[tid] = 0u;
    if (tid < 128) {
        int gi = i0 + tid; sbi[tid] = (gi < QN) ? g_bin[b * QN + gi] : 0;
    }
    if (tid < 64) {
        int gj = j0 + tid; sbj[tid] = (gj < QN) ? g_bin[b * QN + gj] : 0;
    }
    if (tid == 0) { MBAR_INIT(mb0, 1); MBAR_INIT(mb1, 1); }
    __syncthreads();

    auto issue = [&](int ch, int stage) {
        uint32_t mbar = stage ? mb1 : mb0;
        uint32_t sb = dbu + stage * STAGE_BYTES;
        MBAR_EXPECT(mbar, txBytes);
        const size_t baseA = ((size_t)(b * NCH + ch) * QPAD + i0) * KC;
        bulk_cp(sb,          g_hi + baseA, A_TILE, mbar);
        bulk_cp(sb + A_TILE, g_lo + baseA, A_TILE, mbar);
        if (!diag) {
            const size_t baseB = ((size_t)(b * NCH + ch) * QPAD + j0) * KC;
            bulk_cp(sb + 2 * A_TILE,          g_hi + baseB, B_TILE, mbar);
            bulk_cp(sb + 2 * A_TILE + B_TILE, g_lo + baseB, B_TILE, mbar);
        }
    };

    float acc[8][4];
    #pragma unroll
    for (int i = 0; i < 8; i++)
        #pragma unroll
        for (int e = 0; e < 4; e++) acc[i][e] = 0.0f;

    if (tid == 0) { issue(0, 0); issue(1, 1); }

    const uint32_t aRow = (uint32_t)(moff + (qd & 1) * 8 + t8);
    const uint32_t bRow = (uint32_t)(noff + (qd >> 1) * 8 + t8);
    const uint32_t aCu = (uint32_t)(qd >> 1);
    const uint32_t bCu = (uint32_t)(qd & 1);
    const uint32_t bOff = (uint32_t)(dlt * 64 * 64);  // alias offset within A tile

    #pragma unroll 1
    for (int ch = 0; ch < NCH; ch++) {
        const int st = ch & 1;
        MBAR_WAIT(st ? mb1 : mb0, (ch >> 1) & 1);
        __syncthreads();

        const uint32_t sb = dbu + st * STAGE_BYTES;
        const uint32_t bAh = sb;
        const uint32_t bAl = sb + A_TILE;
        const uint32_t bBh = diag ? (bAh + bOff) : (sb + 2 * A_TILE);
        const uint32_t bBl = diag ? (bAl + bOff) : (sb + 2 * A_TILE + B_TILE);

        #pragma unroll
        for (int ks = 0; ks < 2; ks++) {
            uint32_t bh[8], bl[8];
            #pragma unroll
            for (int ntp = 0; ntp < 2; ntp++) {
                uint32_t row = bRow + ntp * 16;
                uint32_t c = (uint32_t)(ks * 2) + bCu;
                c ^= (row ^ (row >> 2)) & 3u;
                uint32_t off = row * 64 + c * 16;
                ldsm4(bh + ntp * 4, bBh + off);
                ldsm4(bl + ntp * 4, bBl + off);
            }
            #pragma unroll
            for (int mt = 0; mt < 2; mt++) {
                uint32_t row = aRow + mt * 16;
                uint32_t c = (uint32_t)(ks * 2) + aCu;
                c ^= (row ^ (row >> 2)) & 3u;
                uint32_t off = row * 64 + c * 16;
                uint32_t ah[4], al[4];
                ldsm4(ah, bAh + off);
                ldsm4(al, bAl + off);
                #pragma unroll
                for (int nt = 0; nt < 4; nt++) {
                    const uint32_t* bhv = bh + (nt >> 1) * 4 + (nt & 1) * 2;
                    const uint32_t* blv = bl + (nt >> 1) * 4 + (nt & 1) * 2;
                    mma_f16(acc[mt * 4 + nt], ah, bhv);
                    mma_f16(acc[mt * 4 + nt], ah, blv);
                    mma_f16(acc[mt * 4 + nt], al, bhv);
                }
            }
        }
        __syncthreads();
        if (ch + 2 < NCH && tid == 0) issue(ch + 2, st);
    }

    // epilogue: segment argmax + local top4
    unsigned lt[4] = {0u, 0u, 0u, 0u};
    #pragma unroll
    for (int mt = 0; mt < 2; mt++) {
        #pragma unroll
        for (int nt = 0; nt < 4; nt++) {
            #pragma unroll
            for (int e = 0; e < 4; e++) {
                int lrow = moff + mt * 16 + lr + ((e & 2) ? 8 : 0);
                int lcol = noff + nt * 8 + 2 * lc + (e & 1);
                int gi = i0 + lrow, gj = j0 + lcol;
                if (gi < QN && gj < QN && gi < gj) {
                    float v = acc[mt * 4 + nt][e];
                    unsigned ev = encf(v);
                    if (ev > lt[3]) {
                        if (ev > lt[0])      { lt[3]=lt[2]; lt[2]=lt[1]; lt[1]=lt[0]; lt[0]=ev; }
                        else if (ev > lt[1]) { lt[3]=lt[2]; lt[2]=lt[1]; lt[1]=ev; }
                        else if (ev > lt[2]) { lt[3]=lt[2]; lt[2]=ev; }
                        else                 { lt[3]=ev; }
                    }
                    int bi = sbi[lrow], bj = sbj[lcol];
                    int sgm = min(bi, bj) * NBINS + max(bi, bj);
                    unsigned long long key =
                        ((unsigned long long)ev << 32) |
                        (unsigned long long)(0xFFFFFFFFu - (unsigned)(gi * QN + gj));
                    if (key > sseg[sgm]) atomicMax(&sseg[sgm], key);
                }
            }
        }
    }
    #pragma unroll
    for (int q4 = 0; q4 < 4; q4++) {
        unsigned v = lt[q4];
        if (!v) break;
        #pragma unroll
        for (int sl = 0; sl < 4; sl++) {
            if (v > stop4[sl]) {
                unsigned old = atomicMax(&stop4[sl], v);
                v = min(v, old);
            }
            if (!v) break;
        }
    }
    __syncthreads();

    unsigned long long* gs = g_seg + (size_t)b * NB2;
    for (int s = tid; s < NB2; s += 256) {
        unsigned long long k = sseg[s];
        if (k && k > gs[s]) atomicMax(&gs[s], k);
    }
    if (tid == 0) {
        unsigned* gt = g_top4 + b * 4;
        #pragma unroll
        for (int q4 = 0; q4 < 4; q4++) {
            unsigned v = stop4[q4];
            if (!v) continue;
            for (int sl = 0; sl < 4; sl++) {
                if (v > gt[sl]) {
                    unsigned old = atomicMax(&gt[sl], v);
                    v = min(v, old);
                }
                if (!v) break;
            }
        }
    }
    __syncthreads();

    // ---- per-batch completion; last CTA runs finalize ----
    if (tid == 0) {
        __threadfence();
        unsigned old = atomicAdd(&g_bcnt[b], 1u);
        s_isLast = (old == NTPB - 1) ? 1 : 0;
    }
    __syncthreads();
    if (!s_isLast) return;

    FinSmem* fsm = (FinSmem*)dynh;
    const float* ang = g_ang + b * QN;
    const float TWO_PI_F  = 6.283185307179586f;
    const float HALF_PI_F = 1.5707963267948966f;

    for (int s = tid; s < NB2; s += 256) {
        unsigned long long key = __ldcg(&g_seg[(size_t)b * NB2 + s]);
        float v = 0.f, ai = 0.f, aj = 0.f, d = 0.f;
        unsigned char vl = 0;
        if (key) {
            vl = 1;
            v = decf((unsigned)(key >> 32));
            unsigned ij = 0xFFFFFFFFu - (unsigned)key;
            int i = ij / QN, j = ij - i * QN;
            ai = ang[i]; aj = ang[j];
            float diff = fabsf(ai - aj);
            d = fminf(fminf(diff, TWO_PI_F - diff), HALF_PI_F);
        }
        fsm->ssel[s] = v; fsm->sai[s] = ai; fsm->saj[s] = aj;
        fsm->sdd[s] = d; fsm->svld[s] = vl;
    }
    __syncthreads();

    int c = 0; unsigned m1 = 0, m2 = 0;
    for (int s = tid; s < NB2; s += 256) {
        if (fsm->svld[s]) {
            c++;
            unsigned e = encf(fsm->ssel[s]);
            if (e > m1) { m2 = m1; m1 = e; } else if (e > m2) m2 = e;
        }
    }
    int S = bsumi(c, fsm->shi, tid);
    unsigned t1, t2; btop2(m1, m2, fsm->sh1, fsm->sh2, tid, t1, t2);
    float thr = quant2(decf(t1), decf(t2), S);

    c = 0;
    for (int s = tid; s < NB2; s += 256) {
        unsigned char m = (fsm->svld[s] && fsm->ssel[s] > thr) ? 1 : 0;
        fsm->smF[s] = m; c += m;
    }
    int c1 = bsumi(c, fsm->shi, tid);

    float th2 = decf(__ldcg(&g_top4[b * 4 + 3]));
    bool use_fb = (c1 < 2);
    c = 0;
    for (int s = tid; s < NB2; s += 256) {
        unsigned char m = use_fb ? ((fsm->svld[s] && fsm->ssel[s] >= th2) ? 1 : 0)
                                 : fsm->smF[s];
        fsm->smF[s] = m; c += m;
    }
    int cnt = bsumi(c, fsm->shi, tid);

    float med = BIGV;
    if (cnt > 0) {
        int kk = (cnt - 1) >> 1;
        unsigned prefix = 0;
        const int flane = tid & 31, w = tid >> 5;
        #pragma unroll
        for (int shift = 24; shift >= 0; shift -= 8) {
            fsm->hist[tid] = 0;
            __syncthreads();
            for (int s = tid; s < NB2; s += 256) {
                if (fsm->smF[s]) {
                    unsigned key = __float_as_uint(fsm->sdd[s]);
                    bool in = (shift == 24) || ((key >> (shift + 8)) == prefix);
                    if (in) atomicAdd(&fsm->hist[(key >> shift) & 255u], 1u);
                }
            }
            __syncthreads();
            unsigned my = fsm->hist[tid];
            unsigned v = my;
            #pragma unroll
            for (int o = 1; o < 32; o <<= 1) {
                unsigned u = __shfl_up_sync(0xffffffffu, v, o);
                if (flane >= o) v += u;
            }
            if (flane == 31) fsm->warpTot[w] = v;
            __syncthreads();
            unsigned off = 0;
            #pragma unroll
            for (int ww = 0; ww < 8; ww++) off += (ww < w) ? fsm->warpTot[ww] : 0u;
            unsigned cum = v + off, bef = cum - my;
            if ((int)cum > kk && (int)bef <= kk) { fsm->s_dig = (unsigned)tid; fsm->s_bef = bef; }
            __syncthreads();
            prefix = (prefix << 8) | fsm->s_dig;
            kk -= (int)fsm->s_bef;
            __syncthreads();
        }
        med = __uint_as_float(prefix);
    }
    float alpha = fminf(fmaxf(med, (float)(3.14159265358979323846 / 36.0)), HALF_PI_F);
    __syncthreads();

    float fs = 0.f; int nc = 0;
    for (int s = tid; s < NB2; s += 256) {
        if (fsm->smF[s] && fsm->sdd[s] <= alpha) {
            float ai = fsm->sai[s], aj = fsm->saj[s];
            float mean = atan2f((sinf(ai) + sinf(aj)) * 0.5f,
                                (cosf(ai) + cosf(aj)) * 0.5f);
            float d1 = fabsf(ai - mean); d1 = fminf(fminf(d1, TWO_PI_F - d1), HALF_PI_F);
            float d2 = fabsf(aj - mean); d2 = fminf(fminf(d2, TWO_PI_F - d2), HALF_PI_F);
            fs += d1 * d1 + d2 * d2;
            nc++;
        }
    }
    float coop_sum = bsumf(fs, fsm->shf, tid);
    int n_coop = bsumi(nc, fsm->shi, tid);
    float coop_b = coop_sum / (float)max(n_coop, 1);

    c = 0; m1 = 0; m2 = 0;
    for (int s = tid; s < NB2; s += 256) {
        if (fsm->smF[s] && fsm->sdd[s] > alpha) {
            c++;
            unsigned e = encf(fsm->ssel[s]);
            if (e > m1) { m2 = m1; m1 = e; } else if (e > m2) m2 = e;
        }
    }
    int n_comp = bsumi(c, fsm->shi, tid);
    btop2(m1, m2, fsm->sh1, fsm->sh2, tid, t1, t2);
    float margin = quant2(decf(t1), decf(t2), n_comp);

    fs = 0.f;
    for (int s = tid; s < NB2; s += 256) {
        if (fsm->smF[s] && fsm->sdd[s] > alpha) {
            float viol = fmaxf(fsm->ssel[s] - margin, 0.f);
            fs += viol * viol;
        }
    }
    float comp_sum = bsumf(fs, fsm->shf, tid);
    float comp_b = comp_sum / (float)max(n_comp, 1);

    if (tid == 0) {
        g_res[b * 4 + 0] = coop_b;
        g_res[b * 4 + 1] = comp_b;
        g_res[b * 4 + 2] = (cnt > 0) ? 1.0f : 0.0f;
        __threadfence();
        unsigned old = atomicAdd(&g_done, 1u);
        if (old == NBATCH - 1) {
            float cs = 0.f, ps = 0.f; int nv = 0;
            for (int bb = 0; bb < NBATCH; bb++) {
                float r0 = __ldcg(&g_res[bb * 4 + 0]);
                float r1 = __ldcg(&g_res[bb * 4 + 1]);
                float r2 = __ldcg(&g_res[bb * 4 + 2]);
                cs += r0; ps += r1;
                nv += (r2 > 0.f) ? 1 : 0;
            }
            float denom = (float)max(nv, 1);
            out[0] = cs / denom;
            out[1] = ps / denom;
        }
    }
}

// ---------------- launch ----------------
extern "C" void kernel_launch(void* const* d_in, const int* in_sizes, int n_in,
                              void* d_out, int out_size) {
    const float* qf = (const float*)d_in[0];   // [16,900,256]
    const float* pa = (const float*)d_in[1];   // [16,900,2]
    const float* W  = (const float*)d_in[2];   // [36,256]
    float* out = (float*)d_out;

    cudaFuncSetAttribute(k_pair, cudaFuncAttributeMaxDynamicSharedMemorySize, DYN_SMEM);

    k_fuse<<<NBATCH * QPAD / 8, 256>>>(qf, pa, W);
    dim3 g2(NTPB, NBATCH);
    k_pair<<<g2, 256, DYN_SMEM>>>(out);
}

// round 17
// speedup vs baseline: 1.0791x; 1.0240x over previous
#include <cuda_runtime.h>
#include <cuda_fp16.h>
#include <math.h>
#include <stdint.h>

#define NBATCH 16
#define QN 900
#define QPAD 1024
#define HID 256
#define NBINS 36
#define NB2 1296
#define BIGV 1e9f

#define KC 32
#define NCH (HID / KC)       // 8
#define NTJ 15               // 64-col tiles that contain real data (j0 <= 896)
#define NTPB 64              // tiles per batch: sum_{ti=0..7}(15-2ti)
#define A_TILE 8192          // 128 rows x 32 halves x 2B
#define B_TILE 4096          // 64 rows x 32 halves x 2B
#define STAGE_BYTES (2 * A_TILE + 2 * B_TILE)   // 24576
#define DYN_SMEM (2 * STAGE_BYTES)              // 49152

// ---------------- device globals ----------------
// chunk-major: [batch][chunk][row(QPAD)][32 halves]
__device__ __half g_hi[NBATCH * NCH * QPAD * KC];
__device__ __half g_lo[NBATCH * NCH * QPAD * KC];
__device__ float g_ang[NBATCH * QN];
__device__ int   g_bin[NBATCH * QN];
__device__ unsigned long long g_seg[NBATCH * NB2];
__device__ unsigned int g_top4[NBATCH * 4];
__device__ float g_res[NBATCH * 4];
__device__ unsigned int g_bcnt[NBATCH];
__device__ unsigned int g_done;

// ---------------- ordered-float encoding ----------------
__device__ __forceinline__ unsigned encf(float f) {
    unsigned u = __float_as_uint(f);
    return (u & 0x80000000u) ? ~u : (u | 0x80000000u);
}
__device__ __forceinline__ float decf(unsigned u) {
    unsigned v = (u & 0x80000000u) ? (u ^ 0x80000000u) : ~u;
    return __uint_as_float(v);
}
__device__ __forceinline__ uint32_t smem_u32(const void* p) {
    uint32_t a;
    asm("{ .reg .u64 t; cvta.to.shared.u64 t, %1; cvt.u32.u64 %0, t; }"
        : "=r"(a) : "l"(p));
    return a;
}
__device__ __forceinline__ void mma_f16(float d[4], const uint32_t a[4],
                                        const uint32_t b[2]) {
    asm volatile(
        "mma.sync.aligned.m16n8k16.row.col.f32.f16.f16.f32 "
        "{%0,%1,%2,%3}, {%4,%5,%6,%7}, {%8,%9}, {%0,%1,%2,%3};"
        : "+f"(d[0]), "+f"(d[1]), "+f"(d[2]), "+f"(d[3])
        : "r"(a[0]), "r"(a[1]), "r"(a[2]), "r"(a[3]), "r"(b[0]), "r"(b[1]));
}
__device__ __forceinline__ void ldsm4(uint32_t r[4], uint32_t addr) {
    asm volatile("ldmatrix.sync.aligned.m8n8.x4.shared.b16 {%0,%1,%2,%3}, [%4];"
        : "=r"(r[0]), "=r"(r[1]), "=r"(r[2]), "=r"(r[3]) : "r"(addr));
}
__device__ __forceinline__ void bulk_cp(uint32_t dst, const void* src,
                                        uint32_t bytes, uint32_t mbar) {
    asm volatile(
        "cp.async.bulk.shared::cta.global.mbarrier::complete_tx::bytes "
        "[%0], [%1], %2, [%3];"
        :: "r"(dst), "l"(src), "r"(bytes), "r"(mbar) : "memory");
}
#define MBAR_INIT(mbar, cnt) \
    asm volatile("mbarrier.init.shared.b64 [%0], %1;" :: "r"(mbar), "r"((uint32_t)(cnt)) : "memory")
#define MBAR_EXPECT(mbar, tx) \
    asm volatile("mbarrier.arrive.expect_tx.shared.b64 _, [%0], %1;" \
                 :: "r"(mbar), "r"((uint32_t)(tx)) : "memory")
#define MBAR_WAIT(mbar, par) do { \
    uint32_t _m = (mbar), _p = (par), _d; \
    asm volatile("{\n\t.reg .pred p;\n\t" \
        "mbarrier.try_wait.parity.acquire.cta.shared::cta.b64 p, [%1], %2;\n\t" \
        "selp.b32 %0, 1, 0, p;\n\t}" : "=r"(_d) : "r"(_m), "r"(_p) : "memory"); \
    if (!_d) { \
        asm volatile("{\n\t.reg .pred P1;\n\t" \
            "WL_%=:\n\t" \
            "mbarrier.try_wait.parity.acquire.cta.shared::cta.b64 P1, [%0], %1, 0x989680;\n\t" \
            "@P1 bra.uni WD_%=;\n\t" \
            "bra.uni WL_%=;\n\t" \
            "WD_%=:\n\t}" :: "r"(_m), "r"(_p) : "memory"); \
    } \
} while (0)

// ---------------- fuse: init + bins + normalize + hi/lo split (chunk-major, swizzled) ----------------
__global__ __launch_bounds__(256) void k_fuse(const float* __restrict__ qf,
                                              const float* __restrict__ pa,
                                              const float* __restrict__ W) {
    __shared__ int sbin[8];
    const int gid = blockIdx.x * 256 + threadIdx.x;
    if (gid < NBATCH * NB2) g_seg[gid] = 0ULL;
    if (gid < NBATCH * 4)   g_top4[gid] = 0u;
    if (gid < NBATCH)       g_bcnt[gid] = 0u;
    if (gid == 0)           g_done = 0u;

    const int warp = threadIdx.x >> 5;
    const int lane = threadIdx.x & 31;
    const int row0 = blockIdx.x * 8;

    if (threadIdx.x < 8) {
        int row = row0 + threadIdx.x;
        int b = row >> 10, q = row & (QPAD - 1);
        int bin = 0;
        if (q < QN) {
            int bq = b * QN + q;
            float x = pa[bq * 2 + 0], y = pa[bq * 2 + 1];
            float a = (float)atan2((double)y, (double)x);
            const float TWO_PI_F = 6.283185307179586f;
            if (a < 0.0f) a += TWO_PI_F;
            const float BIN_SIZE_F = (float)(6.283185307179586476925287 / 36.0);
            bin = (int)(a / BIN_SIZE_F);
            bin = min(max(bin, 0), NBINS - 1);
            g_ang[bq] = a; g_bin[bq] = bin;
        }
        sbin[threadIdx.x] = bin;
    }
    __syncthreads();

    const int row = row0 + warp;
    const int b = row >> 10, q = row & (QPAD - 1);

    const int ch = lane >> 2, cu = lane & 3;
    const int cs = cu ^ ((q ^ (q >> 2)) & 3);
    const size_t doff = (((size_t)(b * NCH + ch) * QPAD + q) * KC) + cs * 8;

    if (q >= QN) {
        uint4 z = make_uint4(0, 0, 0, 0);
        *(uint4*)(g_hi + doff) = z;
        *(uint4*)(g_lo + doff) = z;
        return;
    }
    const int bq = b * QN + q;
    const int bin = sbin[warp];

    const float4* qr = (const float4*)(qf + (size_t)bq * HID);
    const float4* wr = (const float4*)(W + (size_t)bin * HID);
    float4 f0 = qr[2 * lane], f1 = qr[2 * lane + 1];
    float4 w0 = wr[2 * lane], w1 = wr[2 * lane + 1];
    f0.x += w0.x; f0.y += w0.y; f0.z += w0.z; f0.w += w0.w;
    f1.x += w1.x; f1.y += w1.y; f1.z += w1.z; f1.w += w1.w;
    float ss = f0.x*f0.x + f0.y*f0.y + f0.z*f0.z + f0.w*f0.w
             + f1.x*f1.x + f1.y*f1.y + f1.z*f1.z + f1.w*f1.w;
    #pragma unroll
    for (int o = 16; o; o >>= 1) ss += __shfl_xor_sync(0xffffffffu, ss, o);
    float nrm = fmaxf(sqrtf(ss), 1e-12f);

    float v[8] = {f0.x, f0.y, f0.z, f0.w, f1.x, f1.y, f1.z, f1.w};
    __half oh[8], ol[8];
    #pragma unroll
    for (int i = 0; i < 8; i++) {
        float x = v[i] / nrm;
        __half h = __float2half_rn(x);
        float lo = x - __half2float(h);
        oh[i] = h;
        ol[i] = __float2half_rn(lo);
    }
    *(uint4*)(g_hi + doff) = *(const uint4*)oh;
    *(uint4*)(g_lo + doff) = *(const uint4*)ol;
}

// ---------------- block-reduce helpers (256 threads) ----------------
__device__ __forceinline__ float bsumf(float v, float* sh8, int tid) {
    #pragma unroll
    for (int o = 16; o; o >>= 1) v += __shfl_xor_sync(0xffffffffu, v, o);
    if ((tid & 31) == 0) sh8[tid >> 5] = v;
    __syncthreads();
    float r = sh8[0]+sh8[1]+sh8[2]+sh8[3]+sh8[4]+sh8[5]+sh8[6]+sh8[7];
    __syncthreads();
    return r;
}
__device__ __forceinline__ int bsumi(int v, int* sh8, int tid) {
    #pragma unroll
    for (int o = 16; o; o >>= 1) v += __shfl_xor_sync(0xffffffffu, v, o);
    if ((tid & 31) == 0) sh8[tid >> 5] = v;
    __syncthreads();
    int r = sh8[0]+sh8[1]+sh8[2]+sh8[3]+sh8[4]+sh8[5]+sh8[6]+sh8[7];
    __syncthreads();
    return r;
}
__device__ __forceinline__ void btop2(unsigned m1, unsigned m2,
                                      unsigned* s1, unsigned* s2, int tid,
                                      unsigned& o1, unsigned& o2) {
    #pragma unroll
    for (int o = 16; o; o >>= 1) {
        unsigned u1 = __shfl_xor_sync(0xffffffffu, m1, o);
        unsigned u2 = __shfl_xor_sync(0xffffffffu, m2, o);
        unsigned n1 = max(m1, u1);
        unsigned n2 = max(min(m1, u1), max(m2, u2));
        m1 = n1; m2 = n2;
    }
    if ((tid & 31) == 0) { s1[tid >> 5] = m1; s2[tid >> 5] = m2; }
    __syncthreads();
    unsigned t1 = 0, t2 = 0;
    #pragma unroll
    for (int w = 0; w < 8; w++) {
        unsigned a = s1[w], bb = s2[w];
        unsigned n1 = max(t1, a);
        unsigned n2 = max(min(t1, a), max(t2, bb));
        t1 = n1; t2 = n2;
    }
    __syncthreads();
    o1 = t1; o2 = t2;
}
__device__ __forceinline__ float quant2(float vmax, float vsec, int n) {
    if (n <= 0) return BIGV;
    float nf = (float)n;
    float q  = 1.0f - 1.0f / (nf + 1.0f);
    float pos = q * fmaxf(nf - 1.0f, 0.0f);
    int lo = (int)floorf(pos); lo = min(max(lo, 0), NB2 - 1);
    int hi = (int)ceilf(pos);  hi = min(max(hi, 0), NB2 - 1);
    float frac = pos - (float)lo;
    float vlo = (lo >= n - 1) ? vmax : vsec;
    float vhi = (hi >= n - 1) ? vmax : vsec;
    return vlo + (vhi - vlo) * frac;
}

// finalize shared-memory overlay on dynamic smem (GEMM buffers dead)
struct FinSmem {
    float ssel[NB2], sdd[NB2], sai[NB2], saj[NB2];
    unsigned char svld[NB2], smF[NB2];
    float shf[8];
    int   shi[8];
    unsigned sh1[8], sh2[8];
    unsigned hist[256];
    unsigned warpTot[8];
    unsigned s_dig, s_bef;
};

// ---------------- pair kernel: 128x64 tiles (pruned grid), 3 CTAs/SM ----------------
__global__ __launch_bounds__(256, 3) void k_pair(float* __restrict__ out) {
    __shared__ unsigned long long sseg[NB2];
    __shared__ int sbi[128], sbj[64];
    __shared__ unsigned stop4[4];
    __shared__ int s_isLast;
    __shared__ __align__(8) unsigned long long s_mbar[2];
    extern __shared__ __half dynh[];
    const uint32_t dbu = smem_u32(dynh);
    const uint32_t mb0 = smem_u32(&s_mbar[0]);
    const uint32_t mb1 = smem_u32(&s_mbar[1]);

    const int b = blockIdx.y;
    int p = blockIdx.x;
    int ti = 0, rem = p;
    while (rem >= NTJ - 2 * ti) { rem -= NTJ - 2 * ti; ti++; }
    const int cj = 2 * ti + rem;
    const int i0 = ti * 128, j0 = cj * 64;
    const int dlt = cj - 2 * ti;              // 0/1 -> B aliases A
    const bool diag = (dlt < 2);
    const uint32_t txBytes = diag ? (2 * A_TILE) : (2 * A_TILE + 2 * B_TILE);

    const int tid = threadIdx.x, wid = tid >> 5, lane = tid & 31;
    const int moff = (wid >> 1) * 32, noff = (wid & 1) * 32;
    const int lr = lane >> 2, lc = lane & 3;
    const int t8 = lane & 7, qd = lane >> 3;

    for (int s = tid; s < NB2; s += 256) sseg[s] = 0ULL;
    if (tid < 4) stop4[tid] = 0u;
    if (tid < 128) {
        int gi = i0 + tid; sbi[tid] = (gi < QN) ? g_bin[b * QN + gi] : 0;
    }
    if (tid < 64) {
        int gj = j0 + tid; sbj[tid] = (gj < QN) ? g_bin[b * QN + gj] : 0;
    }
    if (tid == 0) { MBAR_INIT(mb0, 1); MBAR_INIT(mb1, 1); }
    __syncthreads();

    auto issue = [&](int ch, int stage) {
        uint32_t mbar = stage ? mb1 : mb0;
        uint32_t sb = dbu + stage * STAGE_BYTES;
        MBAR_EXPECT(mbar, txBytes);
        const size_t baseA = ((size_t)(b * NCH + ch) * QPAD + i0) * KC;
        bulk_cp(sb,          g_hi + baseA, A_TILE, mbar);
        bulk_cp(sb + A_TILE, g_lo + baseA, A_TILE, mbar);
        if (!diag) {
            const size_t baseB = ((size_t)(b * NCH + ch) * QPAD + j0) * KC;
            bulk_cp(sb + 2 * A_TILE,          g_hi + baseB, B_TILE, mbar);
            bulk_cp(sb + 2 * A_TILE + B_TILE, g_lo + baseB, B_TILE, mbar);
        }
    };

    float acc[8][4];
    #pragma unroll
    for (int i = 0; i < 8; i++)
        #pragma unroll
        for (int e = 0; e < 4; e++) acc[i][e] = 0.0f;

    if (tid == 0) { issue(0, 0); issue(1, 1); }

    const uint32_t aRow = (uint32_t)(moff + (qd & 1) * 8 + t8);
    const uint32_t bRow = (uint32_t)(noff + (qd >> 1) * 8 + t8);
    const uint32_t aCu = (uint32_t)(qd >> 1);
    const uint32_t bCu = (uint32_t)(qd & 1);
    const uint32_t bOff = (uint32_t)(dlt * 64 * 64);  // alias offset within A tile

    #pragma unroll 1
    for (int ch = 0; ch < NCH; ch++) {
        const int st = ch & 1;
        MBAR_WAIT(st ? mb1 : mb0, (ch >> 1) & 1);
        __syncthreads();

        const uint32_t sb = dbu + st * STAGE_BYTES;
        const uint32_t bAh = sb;
        const uint32_t bAl = sb + A_TILE;
        const uint32_t bBh = diag ? (bAh + bOff) : (sb + 2 * A_TILE);
        const uint32_t bBl = diag ? (bAl + bOff) : (sb + 2 * A_TILE + B_TILE);

        #pragma unroll
        for (int ks = 0; ks < 2; ks++) {
            uint32_t bh[8], bl[8];
            #pragma unroll
            for (int ntp = 0; ntp < 2; ntp++) {
                uint32_t row = bRow + ntp * 16;
                uint32_t c = (uint32_t)(ks * 2) + bCu;
                c ^= (row ^ (row >> 2)) & 3u;
                uint32_t off = row * 64 + c * 16;
                ldsm4(bh + ntp * 4, bBh + off);
                ldsm4(bl + ntp * 4, bBl + off);
            }
            #pragma unroll
            for (int mt = 0; mt < 2; mt++) {
                uint32_t row = aRow + mt * 16;
                uint32_t c = (uint32_t)(ks * 2) + aCu;
                c ^= (row ^ (row >> 2)) & 3u;
                uint32_t off = row * 64 + c * 16;
                uint32_t ah[4], al[4];
                ldsm4(ah, bAh + off);
                ldsm4(al, bAl + off);
                #pragma unroll
                for (int nt = 0; nt < 4; nt++) {
                    const uint32_t* bhv = bh + (nt >> 1) * 4 + (nt & 1) * 2;
                    const uint32_t* blv = bl + (nt >> 1) * 4 + (nt & 1) * 2;
                    mma_f16(acc[mt * 4 + nt], ah, bhv);
                    mma_f16(acc[mt * 4 + nt], ah, blv);
                    mma_f16(acc[mt * 4 + nt], al, bhv);
                }
            }
        }
        __syncthreads();
        if (ch + 2 < NCH && tid == 0) issue(ch + 2, st);
    }

    // epilogue: segment argmax + local top4
    unsigned lt[4] = {0u, 0u, 0u, 0u};
    #pragma unroll
    for (int mt = 0; mt < 2; mt++) {
        #pragma unroll
        for (int nt = 0; nt < 4; nt++) {
            #pragma unroll
            for (int e = 0; e < 4; e++) {
                int lrow = moff + mt * 16 + lr + ((e & 2) ? 8 : 0);
                int lcol = noff + nt * 8 + 2 * lc + (e & 1);
                int gi = i0 + lrow, gj = j0 + lcol;
                if (gi < QN && gj < QN && gi < gj) {
                    float v = acc[mt * 4 + nt][e];
                    unsigned ev = encf(v);
                    if (ev > lt[3]) {
                        if (ev > lt[0])      { lt[3]=lt[2]; lt[2]=lt[1]; lt[1]=lt[0]; lt[0]=ev; }
                        else if (ev > lt[1]) { lt[3]=lt[2]; lt[2]=lt[1]; lt[1]=ev; }
                        else if (ev > lt[2]) { lt[3]=lt[2]; lt[2]=ev; }
                        else                 { lt[3]=ev; }
                    }
                    int bi = sbi[lrow], bj = sbj[lcol];
                    int sgm = min(bi, bj) * NBINS + max(bi, bj);
                    unsigned long long key =
                        ((unsigned long long)ev << 32) |
                        (unsigned long long)(0xFFFFFFFFu - (unsigned)(gi * QN + gj));
                    if (key > sseg[sgm]) atomicMax(&sseg[sgm], key);
                }
            }
        }
    }
    #pragma unroll
    for (int q4 = 0; q4 < 4; q4++) {
        unsigned v = lt[q4];
        if (!v) break;
        #pragma unroll
        for (int sl = 0; sl < 4; sl++) {
            if (v > stop4[sl]) {
                unsigned old = atomicMax(&stop4[sl], v);
                v = min(v, old);
            }
            if (!v) break;
        }
    }
    __syncthreads();

    unsigned long long* gs = g_seg + (size_t)b * NB2;
    for (int s = tid; s < NB2; s += 256) {
        unsigned long long k = sseg[s];
        if (k && k > gs[s]) atomicMax(&gs[s], k);
    }
    if (tid == 0) {
        unsigned* gt = g_top4 + b * 4;
        #pragma unroll
        for (int q4 = 0; q4 < 4; q4++) {
            unsigned v = stop4[q4];
            if (!v) continue;
            for (int sl = 0; sl < 4; sl++) {
                if (v > gt[sl]) {
                    unsigned old = atomicMax(&gt[sl], v);
                    v = min(v, old);
                }
                if (!v) break;
            }
        }
    }
    __syncthreads();

    // ---- per-batch completion; last CTA runs finalize ----
    if (tid == 0) {
        __threadfence();
        unsigned old = atomicAdd(&g_bcnt[b], 1u);
        s_isLast = (old == NTPB - 1) ? 1 : 0;
    }
    __syncthreads();
    if (!s_isLast) return;

    FinSmem* fsm = (FinSmem*)dynh;
    const float* ang = g_ang + b * QN;
    const float TWO_PI_F  = 6.283185307179586f;
    const float HALF_PI_F = 1.5707963267948966f;

    for (int s = tid; s < NB2; s += 256) {
        unsigned long long key = __ldcg(&g_seg[(size_t)b * NB2 + s]);
        float v = 0.f, ai = 0.f, aj = 0.f, d = 0.f;
        unsigned char vl = 0;
        if (key) {
            vl = 1;
            v = decf((unsigned)(key >> 32));
            unsigned ij = 0xFFFFFFFFu - (unsigned)key;
            int i = ij / QN, j = ij - i * QN;
            ai = ang[i]; aj = ang[j];
            float diff = fabsf(ai - aj);
            d = fminf(fminf(diff, TWO_PI_F - diff), HALF_PI_F);
        }
        fsm->ssel[s] = v; fsm->sai[s] = ai; fsm->saj[s] = aj;
        fsm->sdd[s] = d; fsm->svld[s] = vl;
    }
    __syncthreads();

    int c = 0; unsigned m1 = 0, m2 = 0;
    for (int s = tid; s < NB2; s += 256) {
        if (fsm->svld[s]) {
            c++;
            unsigned e = encf(fsm->ssel[s]);
            if (e > m1) { m2 = m1; m1 = e; } else if (e > m2) m2 = e;
        }
    }
    int S = bsumi(c, fsm->shi, tid);
    unsigned t1, t2; btop2(m1, m2, fsm->sh1, fsm->sh2, tid, t1, t2);
    float thr = quant2(decf(t1), decf(t2), S);

    c = 0;
    for (int s = tid; s < NB2; s += 256) {
        unsigned char m = (fsm->svld[s] && fsm->ssel[s] > thr) ? 1 : 0;
        fsm->smF[s] = m; c += m;
    }
    int c1 = bsumi(c, fsm->shi, tid);

    float th2 = decf(__ldcg(&g_top4[b * 4 + 3]));
    bool use_fb = (c1 < 2);
    c = 0;
    for (int s = tid; s < NB2; s += 256) {
        unsigned char m = use_fb ? ((fsm->svld[s] && fsm->ssel[s] >= th2) ? 1 : 0)
                                 : fsm->smF[s];
        fsm->smF[s] = m; c += m;
    }
    int cnt = bsumi(c, fsm->shi, tid);

    float med = BIGV;
    if (cnt > 0) {
        int kk = (cnt - 1) >> 1;
        unsigned prefix = 0;
        const int flane = tid & 31, w = tid >> 5;
        #pragma unroll
        for (int shift = 24; shift >= 0; shift -= 8) {
            fsm->hist[tid] = 0;
            __syncthreads();
            for (int s = tid; s < NB2; s += 256) {
                if (fsm->smF[s]) {
                    unsigned key = __float_as_uint(fsm->sdd[s]);
                    bool in = (shift == 24) || ((key >> (shift + 8)) == prefix);
                    if (in) atomicAdd(&fsm->hist[(key >> shift) & 255u], 1u);
                }
            }
            __syncthreads();
            unsigned my = fsm->hist[tid];
            unsigned v = my;
            #pragma unroll
            for (int o = 1; o < 32; o <<= 1) {
                unsigned u = __shfl_up_sync(0xffffffffu, v, o);
                if (flane >= o) v += u;
            }
            if (flane == 31) fsm->warpTot[w] = v;
            __syncthreads();
            unsigned off = 0;
            #pragma unroll
            for (int ww = 0; ww < 8; ww++) off += (ww < w) ? fsm->warpTot[ww] : 0u;
            unsigned cum = v + off, bef = cum - my;
            if ((int)cum > kk && (int)bef <= kk) { fsm->s_dig = (unsigned)tid; fsm->s_bef = bef; }
            __syncthreads();
            prefix = (prefix << 8) | fsm->s_dig;
            kk -= (int)fsm->s_bef;
            __syncthreads();
        }
        med = __uint_as_float(prefix);
    }
    float alpha = fminf(fmaxf(med, (float)(3.14159265358979323846 / 36.0)), HALF_PI_F);
    __syncthreads();

    float fs = 0.f; int nc = 0;
    for (int s = tid; s < NB2; s += 256) {
        if (fsm->smF[s] && fsm->sdd[s] <= alpha) {
            float ai = fsm->sai[s], aj = fsm->saj[s];
            float mean = atan2f((sinf(ai) + sinf(aj)) * 0.5f,
                                (cosf(ai) + cosf(aj)) * 0.5f);
            float d1 = fabsf(ai - mean); d1 = fminf(fminf(d1, TWO_PI_F - d1), HALF_PI_F);
            float d2 = fabsf(aj - mean); d2 = fminf(fminf(d2, TWO_PI_F - d2), HALF_PI_F);
            fs += d1 * d1 + d2 * d2;
            nc++;
        }
    }
    float coop_sum = bsumf(fs, fsm->shf, tid);
    int n_coop = bsumi(nc, fsm->shi, tid);
    float coop_b = coop_sum / (float)max(n_coop, 1);

    c = 0; m1 = 0; m2 = 0;
    for (int s = tid; s < NB2; s += 256) {
        if (fsm->smF[s] && fsm->sdd[s] > alpha) {
            c++;
            unsigned e = encf(fsm->ssel[s]);
            if (e > m1) { m2 = m1; m1 = e; } else if (e > m2) m2 = e;
        }
    }
    int n_comp = bsumi(c, fsm->shi, tid);
    btop2(m1, m2, fsm->sh1, fsm->sh2, tid, t1, t2);
    float margin = quant2(decf(t1), decf(t2), n_comp);

    fs = 0.f;
    for (int s = tid; s < NB2; s += 256) {
        if (fsm->smF[s] && fsm->sdd[s] > alpha) {
            float viol = fmaxf(fsm->ssel[s] - margin, 0.f);
            fs += viol * viol;
        }
    }
    float comp_sum = bsumf(fs, fsm->shf, tid);
    float comp_b = comp_sum / (float)max(n_comp, 1);

    if (tid == 0) {
        g_res[b * 4 + 0] = coop_b;
        g_res[b * 4 + 1] = comp_b;
        g_res[b * 4 + 2] = (cnt > 0) ? 1.0f : 0.0f;
        __threadfence();
        unsigned old = atomicAdd(&g_done, 1u);
        if (old == NBATCH - 1) {
            float cs = 0.f, ps = 0.f; int nv = 0;
            for (int bb = 0; bb < NBATCH; bb++) {
                float r0 = __ldcg(&g_res[bb * 4 + 0]);
                float r1 = __ldcg(&g_res[bb * 4 + 1]);
                float r2 = __ldcg(&g_res[bb * 4 + 2]);
                cs += r0; ps += r1;
                nv += (r2 > 0.f) ? 1 : 0;
            }
            float denom = (float)max(nv, 1);
            out[0] = cs / denom;
            out[1] = ps / denom;
        }
    }
}

// ---------------- launch ----------------
extern "C" void kernel_launch(void* const* d_in, const int* in_sizes, int n_in,
                              void* d_out, int out_size) {
    const float* qf = (const float*)d_in[0];   // [16,900,256]
    const float* pa = (const float*)d_in[1];   // [16,900,2]
    const float* W  = (const float*)d_in[2];   // [36,256]
    float* out = (float*)d_out;

    cudaFuncSetAttribute(k_pair, cudaFuncAttributeMaxDynamicSharedMemorySize, DYN_SMEM);

    k_fuse<<<NBATCH * QPAD / 8, 256>>>(qf, pa, W);
    dim3 g2(NTPB, NBATCH);
    k_pair<<<g2, 256, DYN_SMEM>>>(out);
}